// round 6
// baseline (speedup 1.0000x reference)
#include <cuda_runtime.h>

#define N_NODES 5000
#define BATCH   16
#define FEAT    512
#define NEDGE   160000
#define NCOL    64
#define FCOL    128
#define NTOT    (N_NODES*BATCH)   // 80000

// Scratch (device globals; zero-initialized at module load; no allocation allowed)
__device__ __align__(16) float g_h1 [N_NODES*BATCH*16];
__device__ __align__(16) float g_h2 [N_NODES*BATCH*16];
__device__ int   g_deg [N_NODES];          // zero at entry (re-zeroed in k_gemm1 each run)
__device__ int   g_cursor[N_NODES];        // ditto
__device__ int   g_rowstart[N_NODES+1];
__device__ float g_dinv[N_NODES];
__device__ __align__(16) int2 g_csr[NEDGE];   // x = src node, y = norm (float bits)
__device__ float g_col [BATCH*NCOL];

// ---- packed f32x2 helpers (Blackwell) ----
__device__ __forceinline__ unsigned long long splat2(float x){
    unsigned long long r; asm("mov.b64 %0, {%1, %1};" : "=l"(r) : "f"(x)); return r;
}
__device__ __forceinline__ unsigned long long ffma2(unsigned long long a, unsigned long long b, unsigned long long c){
    unsigned long long d; asm("fma.rn.f32x2 %0, %1, %2, %3;" : "=l"(d) : "l"(a), "l"(b), "l"(c)); return d;
}
__device__ __forceinline__ float2 unpack2(unsigned long long v){
    float2 r; asm("mov.b64 {%0, %1}, %2;" : "=f"(r.x), "=f"(r.y) : "l"(v)); return r;
}
__device__ __forceinline__ float4 shfl4(float4 v, int src){
    float4 r;
    r.x = __shfl_sync(0xffffffffu, v.x, src);
    r.y = __shfl_sync(0xffffffffu, v.y, src);
    r.z = __shfl_sync(0xffffffffu, v.z, src);
    r.w = __shfl_sync(0xffffffffu, v.w, src);
    return r;
}
__device__ __forceinline__ void fma4(float4& a, float nr, const float4& u){
    a.x = fmaf(nr, u.x, a.x); a.y = fmaf(nr, u.y, a.y);
    a.z = fmaf(nr, u.z, a.z); a.w = fmaf(nr, u.w, a.w);
}

// edge_index is INT32 (proven: buffer is 320000*4 bytes; int64 reads crash at its end).
// Layout [2, E]: src = ei[0..E), dst = ei[E..2E).

// ---- degree count: 4 edges per thread via int4 over the dst half ----
__global__ void k_count(const int* __restrict__ ei){
    int e4 = blockIdx.x*blockDim.x + threadIdx.x;
    if (e4 < NEDGE/4){
        int4 v = ((const int4*)(ei + NEDGE))[e4];   // four int32 dsts (byte off 640000, aligned)
        atomicAdd(&g_deg[v.x], 1);
        atomicAdd(&g_deg[v.y], 1);
        atomicAdd(&g_deg[v.z], 1);
        atomicAdd(&g_deg[v.w], 1);
    }
}
// single-block exclusive scan over 5000 degree counts (+ dinv)
__global__ void __launch_bounds__(1024) k_scan(){
    __shared__ int part[1024];
    int t = threadIdx.x;
    const int CH = (N_NODES + 1023) / 1024;   // 5
    int base = t * CH;
    int s = 0;
    #pragma unroll
    for (int j = 0; j < CH; j++){ int idx = base + j; if (idx < N_NODES) s += g_deg[idx]; }
    part[t] = s; __syncthreads();
    for (int off = 1; off < 1024; off <<= 1){
        int v = (t >= off) ? part[t - off] : 0;
        __syncthreads();
        part[t] += v;
        __syncthreads();
    }
    int excl = (t == 0) ? 0 : part[t - 1];
    #pragma unroll
    for (int j = 0; j < CH; j++){
        int idx = base + j;
        if (idx < N_NODES){
            int d = g_deg[idx];
            g_rowstart[idx] = excl; excl += d;
            g_dinv[idx] = rsqrtf((float)(d + 1));
        }
    }
    if (t == 0) g_rowstart[N_NODES] = NEDGE;
}
__global__ void k_fill(const int* __restrict__ ei){
    int e = blockIdx.x*blockDim.x + threadIdx.x;
    if (e >= NEDGE) return;
    int s = ei[e];
    int d = ei[NEDGE + e];
    int pos = atomicAdd(&g_cursor[d], 1);
    float nrm = g_dinv[s] * g_dinv[d];
    g_csr[g_rowstart[d] + pos] = make_int2(s, __float_as_int(nrm));
}

// ---- GEMM1: h1[n][b][0:16] = X[b][n][:] @ W1 (smem-staged X, packed f32x2) ----
#define GR 128
#define KC 16
#define TSTRIDE 20
__global__ void __launch_bounds__(GR) k_gemm1(const float* __restrict__ X, const float* __restrict__ W1){
    __shared__ __align__(16) float ws[FEAT*16];
    __shared__ __align__(16) float tile[GR*TSTRIDE];
    int t = threadIdx.x;
    // re-zero CSR counters for the NEXT run (their last consumer, k_fill, already ran)
    int gid = blockIdx.x*GR + t;
    if (gid < N_NODES){ g_deg[gid] = 0; g_cursor[gid] = 0; }
    for (int i = t; i < FEAT*16/4; i += GR)
        ((float4*)ws)[i] = ((const float4*)W1)[i];
    int row0 = blockIdx.x * GR;                         // 80000 = 625*128, exact
    const float4* Xb = (const float4*)X + (size_t)row0*(FEAT/4);
    unsigned long long acc[8] = {0,0,0,0,0,0,0,0};
    for (int c = 0; c < FEAT/KC; c++){
        __syncthreads();
        #pragma unroll
        for (int i = 0; i < 4; i++){
            int f  = t + GR*i;
            int rr = f >> 2, kq = f & 3;
            float4 v = Xb[(size_t)rr*(FEAT/4) + c*4 + kq];
            *((float4*)&tile[rr*TSTRIDE + kq*4]) = v;
        }
        __syncthreads();
        #pragma unroll
        for (int kq = 0; kq < 4; kq++){
            float4 xv = *((const float4*)&tile[t*TSTRIDE + kq*4]);
            int kbase = c*KC + kq*4;
            #pragma unroll
            for (int kk = 0; kk < 4; kk++){
                float xs = (kk==0)?xv.x:(kk==1)?xv.y:(kk==2)?xv.z:xv.w;
                unsigned long long x2 = splat2(xs);
                const ulonglong2* wk = (const ulonglong2*)&ws[(kbase+kk)*16];
                ulonglong2 w0 = wk[0], w1 = wk[1], w2 = wk[2], w3 = wk[3];
                acc[0]=ffma2(x2,w0.x,acc[0]); acc[1]=ffma2(x2,w0.y,acc[1]);
                acc[2]=ffma2(x2,w1.x,acc[2]); acc[3]=ffma2(x2,w1.y,acc[3]);
                acc[4]=ffma2(x2,w2.x,acc[4]); acc[5]=ffma2(x2,w2.y,acc[5]);
                acc[6]=ffma2(x2,w3.x,acc[6]); acc[7]=ffma2(x2,w3.y,acc[7]);
            }
        }
    }
    int r = row0 + t;
    int b = r / N_NODES, n = r - b*N_NODES;
    float4* dst = (float4*)g_h1 + ((size_t)n*16 + b)*4;
    #pragma unroll
    for (int q = 0; q < 4; q++){
        float2 lo = unpack2(acc[2*q]), hi = unpack2(acc[2*q+1]);
        dst[q] = make_float4(lo.x, lo.y, hi.x, hi.y);
    }
}

// ---- shared gather core: acc = dinv[n]^2*h[n] + sum norm*h[src] ----
__device__ __forceinline__ float4 gather_core(const float4* __restrict__ h, int n, int i){
    float di = g_dinv[n];
    float sl = di * di;
    float4 v = h[n*64 + i];
    float4 acc = make_float4(v.x*sl, v.y*sl, v.z*sl, v.w*sl);
    int k   = g_rowstart[n];
    int end = g_rowstart[n+1];
    for (; k + 8 <= end; k += 8){
        int2 e0 = g_csr[k+0], e1 = g_csr[k+1], e2 = g_csr[k+2], e3 = g_csr[k+3];
        int2 e4 = g_csr[k+4], e5 = g_csr[k+5], e6 = g_csr[k+6], e7 = g_csr[k+7];
        float4 u0 = h[e0.x*64 + i], u1 = h[e1.x*64 + i], u2 = h[e2.x*64 + i], u3 = h[e3.x*64 + i];
        float4 u4 = h[e4.x*64 + i], u5 = h[e5.x*64 + i], u6 = h[e6.x*64 + i], u7 = h[e7.x*64 + i];
        fma4(acc, __int_as_float(e0.y), u0); fma4(acc, __int_as_float(e1.y), u1);
        fma4(acc, __int_as_float(e2.y), u2); fma4(acc, __int_as_float(e3.y), u3);
        fma4(acc, __int_as_float(e4.y), u4); fma4(acc, __int_as_float(e5.y), u5);
        fma4(acc, __int_as_float(e6.y), u6); fma4(acc, __int_as_float(e7.y), u7);
    }
    for (; k + 4 <= end; k += 4){
        int2 e0 = g_csr[k+0], e1 = g_csr[k+1], e2 = g_csr[k+2], e3 = g_csr[k+3];
        float4 u0 = h[e0.x*64 + i], u1 = h[e1.x*64 + i], u2 = h[e2.x*64 + i], u3 = h[e3.x*64 + i];
        fma4(acc, __int_as_float(e0.y), u0); fma4(acc, __int_as_float(e1.y), u1);
        fma4(acc, __int_as_float(e2.y), u2); fma4(acc, __int_as_float(e3.y), u3);
    }
    for (; k < end; k++){
        int2 e = g_csr[k];
        float4 u = h[e.x*64 + i];
        fma4(acc, __int_as_float(e.y), u);
    }
    return acc;
}

// ---- gather layer0 fused with xform: h2 = relu(conv1 + b1) @ W2 ----
// 64 threads/node; lane i: b = i>>2, feature-quarter q = i&3.
__global__ void __launch_bounds__(256) k_gatherX(const float* __restrict__ W2, const float* __restrict__ b1){
    __shared__ float sw[256];
    __shared__ float sb[16];
    sw[threadIdx.x] = W2[threadIdx.x];
    if (threadIdx.x < 16)  sb[threadIdx.x] = b1[threadIdx.x];
    __syncthreads();
    int gt = blockIdx.x*256 + threadIdx.x;
    int n = gt >> 6;
    int i = gt & 63;
    if (n >= N_NODES) return;
    float4 acc = gather_core((const float4*)g_h1, n, i);
    int q = i & 3;
    float4 vv;
    vv.x = fmaxf(acc.x + sb[q*4+0], 0.0f);
    vv.y = fmaxf(acc.y + sb[q*4+1], 0.0f);
    vv.z = fmaxf(acc.z + sb[q*4+2], 0.0f);
    vv.w = fmaxf(acc.w + sb[q*4+3], 0.0f);
    int lane = threadIdx.x & 31;
    int gbase = lane & ~3;
    float o0=0.f, o1=0.f, o2=0.f, o3=0.f;
    #pragma unroll
    for (int jq = 0; jq < 4; jq++){
        float4 u = shfl4(vv, gbase + jq);
        #pragma unroll
        for (int kk = 0; kk < 4; kk++){
            float uj = (kk==0)?u.x:(kk==1)?u.y:(kk==2)?u.z:u.w;
            const float* wr = &sw[(jq*4+kk)*16 + q*4];
            o0 = fmaf(uj, wr[0], o0);
            o1 = fmaf(uj, wr[1], o1);
            o2 = fmaf(uj, wr[2], o2);
            o3 = fmaf(uj, wr[3], o3);
        }
    }
    ((float4*)g_h2)[n*64 + i] = make_float4(o0, o1, o2, o3);
}

// ---- gather layer1 fused with node head + joint broadcast-add output ----
__global__ void __launch_bounds__(256) k_gatherF(const float* __restrict__ b2, const float* __restrict__ fcw,
                                                 const float* __restrict__ fcb, float* __restrict__ out){
    __shared__ __align__(16) float scol[BATCH*NCOL];
    __shared__ float sb2[16], sfw[16], sfcb;
    for (int idx = threadIdx.x; idx < BATCH*NCOL; idx += 256) scol[idx] = g_col[idx];
    if (threadIdx.x < 16){ sb2[threadIdx.x] = b2[threadIdx.x]; sfw[threadIdx.x] = fcw[threadIdx.x]; }
    if (threadIdx.x == 0) sfcb = fcb[0];
    __syncthreads();
    int gt = blockIdx.x*256 + threadIdx.x;
    int n = gt >> 6;
    int i = gt & 63;
    if (n >= N_NODES) return;
    float4 acc = gather_core((const float4*)g_h2, n, i);
    int q = i & 3;
    int b = i >> 2;
    float partial;
    partial  = fmaxf(acc.x + sb2[q*4+0], 0.0f) * sfw[q*4+0];
    partial += fmaxf(acc.y + sb2[q*4+1], 0.0f) * sfw[q*4+1];
    partial += fmaxf(acc.z + sb2[q*4+2], 0.0f) * sfw[q*4+2];
    partial += fmaxf(acc.w + sb2[q*4+3], 0.0f) * sfw[q*4+3];
    partial += __shfl_xor_sync(0xffffffffu, partial, 1);
    partial += __shfl_xor_sync(0xffffffffu, partial, 2);
    float logit = partial + sfcb;
    float4* o = (float4*)(out + (size_t)b*(N_NODES*64) + (size_t)n*64 + q*16);
    const float4* sc = (const float4*)scol + b*16 + q*4;
    #pragma unroll
    for (int c4 = 0; c4 < 4; c4++){
        float4 cv = sc[c4];
        o[c4] = make_float4(logit+cv.x, logit+cv.y, logit+cv.z, logit+cv.w);
    }
}

// ---- column MLP: col_logits[b*64+c] ----
__global__ void __launch_bounds__(256) k_colmlp(const float* __restrict__ CF, const float* __restrict__ cw1,
                                                const float* __restrict__ cb1, const float* __restrict__ cw2,
                                                const float* __restrict__ cb2){
    __shared__ __align__(16) float sw[FCOL*16];
    __shared__ float sb1[16], sw2[16];
    for (int i = threadIdx.x; i < FCOL*16/4; i += 256)
        ((float4*)sw)[i] = ((const float4*)cw1)[i];
    if (threadIdx.x < 16){ sb1[threadIdx.x]=cb1[threadIdx.x]; sw2[threadIdx.x]=cw2[threadIdx.x]; }
    __syncthreads();
    int r = blockIdx.x*256 + threadIdx.x;
    if (r >= BATCH*NCOL) return;
    const float4* xr = (const float4*)CF + (size_t)r*(FCOL/4);
    float acc[16];
    #pragma unroll
    for (int j=0;j<16;j++) acc[j] = sb1[j];
    for (int k4 = 0; k4 < FCOL/4; k4++){
        float4 xv = xr[k4];
        #pragma unroll
        for (int kk=0; kk<4; kk++){
            float xs = (kk==0)?xv.x:(kk==1)?xv.y:(kk==2)?xv.z:xv.w;
            #pragma unroll
            for (int j=0;j<16;j++) acc[j] = fmaf(xs, sw[(k4*4+kk)*16 + j], acc[j]);
        }
    }
    float sres = cb2[0];
    #pragma unroll
    for (int j=0;j<16;j++) sres = fmaf(fmaxf(acc[j], 0.0f), sw2[j], sres);
    g_col[r] = sres;
}

extern "C" void kernel_launch(void* const* d_in, const int* in_sizes, int n_in,
                              void* d_out, int out_size){
    const float* X   = (const float*)d_in[0];
    const float* CF  = (const float*)d_in[1];
    const int*   ei  = (const int*)d_in[2];
    const float* W1  = (const float*)d_in[3];
    const float* b1  = (const float*)d_in[4];
    const float* W2  = (const float*)d_in[5];
    const float* b2  = (const float*)d_in[6];
    const float* fcw = (const float*)d_in[7];
    const float* fcb = (const float*)d_in[8];
    const float* cw1 = (const float*)d_in[9];
    const float* cb1 = (const float*)d_in[10];
    const float* cw2 = (const float*)d_in[11];
    const float* cb2 = (const float*)d_in[12];
    float* out = (float*)d_out;

    k_count <<<(NEDGE/4+255)/256, 256>>>(ei);
    k_scan  <<<1, 1024>>>();
    k_fill  <<<(NEDGE+255)/256, 256>>>(ei);
    k_colmlp<<<4, 256>>>(CF, cw1, cb1, cw2, cb2);
    k_gemm1 <<<NTOT/GR, GR>>>(X, W1);
    k_gatherX<<<(N_NODES*64)/256 + 1, 256>>>(W2, b1);
    k_gatherF<<<(N_NODES*64)/256 + 1, 256>>>(b2, fcw, fcb, out);
}

// round 7
// speedup vs baseline: 1.3861x; 1.3861x over previous
#include <cuda_runtime.h>

#define N_NODES 5000
#define BATCH   16
#define FEAT    512
#define NEDGE   160000
#define NCOL    64
#define FCOL    128
#define NTOT    (N_NODES*BATCH)   // 80000

// Scratch (device globals; zero-initialized at load; no allocation allowed)
__device__ __align__(16) float g_h1  [N_NODES*BATCH*16];
__device__ __align__(16) float g_buf1[N_NODES*BATCH*16];
__device__ __align__(16) float g_h2  [N_NODES*BATCH*16];
__device__ __align__(16) float g_buf2[N_NODES*BATCH*16];
__device__ int   g_deg [N_NODES];          // zero at entry (re-zeroed in k_gemm1 each run)
__device__ int   g_cursor[N_NODES];        // ditto
__device__ int   g_rowstart[N_NODES+1];
__device__ float g_dinv[N_NODES];
__device__ __align__(16) int2 g_csr[NEDGE];   // x = src node, y = norm (float bits)
__device__ float g_col [BATCH*NCOL];

// ---- packed f32x2 helpers (Blackwell) ----
__device__ __forceinline__ unsigned long long splat2(float x){
    unsigned long long r; asm("mov.b64 %0, {%1, %1};" : "=l"(r) : "f"(x)); return r;
}
__device__ __forceinline__ unsigned long long ffma2(unsigned long long a, unsigned long long b, unsigned long long c){
    unsigned long long d; asm("fma.rn.f32x2 %0, %1, %2, %3;" : "=l"(d) : "l"(a), "l"(b), "l"(c)); return d;
}
__device__ __forceinline__ float2 unpack2(unsigned long long v){
    float2 r; asm("mov.b64 {%0, %1}, %2;" : "=f"(r.x), "=f"(r.y) : "l"(v)); return r;
}
__device__ __forceinline__ void fma4(float4& a, float nr, const float4& u){
    a.x = fmaf(nr, u.x, a.x); a.y = fmaf(nr, u.y, a.y);
    a.z = fmaf(nr, u.z, a.z); a.w = fmaf(nr, u.w, a.w);
}

// edge_index is INT32 (proven). Layout [2, E]: src = ei[0..E), dst = ei[E..2E).

// ---- degree count: 4 edges per thread via int4 over the dst half ----
__global__ void k_count(const int* __restrict__ ei){
    int e4 = blockIdx.x*blockDim.x + threadIdx.x;
    if (e4 < NEDGE/4){
        int4 v = ((const int4*)(ei + NEDGE))[e4];
        atomicAdd(&g_deg[v.x], 1);
        atomicAdd(&g_deg[v.y], 1);
        atomicAdd(&g_deg[v.z], 1);
        atomicAdd(&g_deg[v.w], 1);
    }
}
// single-block exclusive scan over 5000 degree counts (+ dinv)
__global__ void __launch_bounds__(1024) k_scan(){
    __shared__ int part[1024];
    int t = threadIdx.x;
    const int CH = (N_NODES + 1023) / 1024;   // 5
    int base = t * CH;
    int s = 0;
    #pragma unroll
    for (int j = 0; j < CH; j++){ int idx = base + j; if (idx < N_NODES) s += g_deg[idx]; }
    part[t] = s; __syncthreads();
    for (int off = 1; off < 1024; off <<= 1){
        int v = (t >= off) ? part[t - off] : 0;
        __syncthreads();
        part[t] += v;
        __syncthreads();
    }
    int excl = (t == 0) ? 0 : part[t - 1];
    #pragma unroll
    for (int j = 0; j < CH; j++){
        int idx = base + j;
        if (idx < N_NODES){
            int d = g_deg[idx];
            g_rowstart[idx] = excl; excl += d;
            g_dinv[idx] = rsqrtf((float)(d + 1));
        }
    }
    if (t == 0) g_rowstart[N_NODES] = NEDGE;
}
// CSR fill: 2 edges per thread via int2 loads
__global__ void k_fill(const int* __restrict__ ei){
    int e2 = blockIdx.x*blockDim.x + threadIdx.x;
    if (e2 >= NEDGE/2) return;
    int2 sp = ((const int2*)ei)[e2];
    int2 dp = ((const int2*)(ei + NEDGE))[e2];
    {
        int pos = atomicAdd(&g_cursor[dp.x], 1);
        g_csr[g_rowstart[dp.x] + pos] = make_int2(sp.x, __float_as_int(g_dinv[sp.x]*g_dinv[dp.x]));
    }
    {
        int pos = atomicAdd(&g_cursor[dp.y], 1);
        g_csr[g_rowstart[dp.y] + pos] = make_int2(sp.y, __float_as_int(g_dinv[sp.y]*g_dinv[dp.y]));
    }
}

// ---- GEMM1: h1[n][b][0:16] = X[b][n][:] @ W1 (smem-staged X, packed f32x2) ----
#define GR 128
#define KC 16
#define TSTRIDE 20
__global__ void __launch_bounds__(GR) k_gemm1(const float* __restrict__ X, const float* __restrict__ W1){
    __shared__ __align__(16) float ws[FEAT*16];
    __shared__ __align__(16) float tile[GR*TSTRIDE];
    int t = threadIdx.x;
    // re-zero CSR counters for the NEXT run (their last consumer, k_fill, already ran)
    int gid = blockIdx.x*GR + t;
    if (gid < N_NODES){ g_deg[gid] = 0; g_cursor[gid] = 0; }
    for (int i = t; i < FEAT*16/4; i += GR)
        ((float4*)ws)[i] = ((const float4*)W1)[i];
    int row0 = blockIdx.x * GR;                         // 80000 = 625*128, exact
    const float4* Xb = (const float4*)X + (size_t)row0*(FEAT/4);
    unsigned long long acc[8] = {0,0,0,0,0,0,0,0};
    for (int c = 0; c < FEAT/KC; c++){
        __syncthreads();
        #pragma unroll
        for (int i = 0; i < 4; i++){
            int f  = t + GR*i;
            int rr = f >> 2, kq = f & 3;
            float4 v = Xb[(size_t)rr*(FEAT/4) + c*4 + kq];
            *((float4*)&tile[rr*TSTRIDE + kq*4]) = v;
        }
        __syncthreads();
        #pragma unroll
        for (int kq = 0; kq < 4; kq++){
            float4 xv = *((const float4*)&tile[t*TSTRIDE + kq*4]);
            int kbase = c*KC + kq*4;
            #pragma unroll
            for (int kk = 0; kk < 4; kk++){
                float xs = (kk==0)?xv.x:(kk==1)?xv.y:(kk==2)?xv.z:xv.w;
                unsigned long long x2 = splat2(xs);
                const ulonglong2* wk = (const ulonglong2*)&ws[(kbase+kk)*16];
                ulonglong2 w0 = wk[0], w1 = wk[1], w2 = wk[2], w3 = wk[3];
                acc[0]=ffma2(x2,w0.x,acc[0]); acc[1]=ffma2(x2,w0.y,acc[1]);
                acc[2]=ffma2(x2,w1.x,acc[2]); acc[3]=ffma2(x2,w1.y,acc[3]);
                acc[4]=ffma2(x2,w2.x,acc[4]); acc[5]=ffma2(x2,w2.y,acc[5]);
                acc[6]=ffma2(x2,w3.x,acc[6]); acc[7]=ffma2(x2,w3.y,acc[7]);
            }
        }
    }
    int r = row0 + t;
    int b = r / N_NODES, n = r - b*N_NODES;
    float4* dst = (float4*)g_h1 + ((size_t)n*16 + b)*4;
    #pragma unroll
    for (int q = 0; q < 4; q++){
        float2 lo = unpack2(acc[2*q]), hi = unpack2(acc[2*q+1]);
        dst[q] = make_float4(lo.x, lo.y, hi.x, hi.y);
    }
}

// ---- gather: buf[n][*] = dinv[n]^2 * h[n][*] + sum_{e: dst=n} norm_e * h[src_e][*] ----
// 64 threads per node (one float4 lane each), 8-deep unrolled edge loop. (R4-proven)
__global__ void __launch_bounds__(256) k_gather(int layer){
    int gt = blockIdx.x*256 + threadIdx.x;
    int n = gt >> 6;
    int i = gt & 63;
    if (n >= N_NODES) return;
    const float4* __restrict__ h  = (const float4*)(layer ? g_h2  : g_h1);
    float4*       __restrict__ bf = (float4*)      (layer ? g_buf2 : g_buf1);
    float di = g_dinv[n];
    float sl = di * di;
    float4 v = h[n*64 + i];
    float4 acc = make_float4(v.x*sl, v.y*sl, v.z*sl, v.w*sl);
    int k   = g_rowstart[n];
    int end = g_rowstart[n+1];
    for (; k + 8 <= end; k += 8){
        int2 e0 = g_csr[k+0], e1 = g_csr[k+1], e2 = g_csr[k+2], e3 = g_csr[k+3];
        int2 e4 = g_csr[k+4], e5 = g_csr[k+5], e6 = g_csr[k+6], e7 = g_csr[k+7];
        float4 u0 = h[e0.x*64 + i], u1 = h[e1.x*64 + i], u2 = h[e2.x*64 + i], u3 = h[e3.x*64 + i];
        float4 u4 = h[e4.x*64 + i], u5 = h[e5.x*64 + i], u6 = h[e6.x*64 + i], u7 = h[e7.x*64 + i];
        fma4(acc, __int_as_float(e0.y), u0); fma4(acc, __int_as_float(e1.y), u1);
        fma4(acc, __int_as_float(e2.y), u2); fma4(acc, __int_as_float(e3.y), u3);
        fma4(acc, __int_as_float(e4.y), u4); fma4(acc, __int_as_float(e5.y), u5);
        fma4(acc, __int_as_float(e6.y), u6); fma4(acc, __int_as_float(e7.y), u7);
    }
    for (; k + 4 <= end; k += 4){
        int2 e0 = g_csr[k+0], e1 = g_csr[k+1], e2 = g_csr[k+2], e3 = g_csr[k+3];
        float4 u0 = h[e0.x*64 + i], u1 = h[e1.x*64 + i], u2 = h[e2.x*64 + i], u3 = h[e3.x*64 + i];
        fma4(acc, __int_as_float(e0.y), u0); fma4(acc, __int_as_float(e1.y), u1);
        fma4(acc, __int_as_float(e2.y), u2); fma4(acc, __int_as_float(e3.y), u3);
    }
    for (; k < end; k++){
        int2 e = g_csr[k];
        float4 u = h[e.x*64 + i];
        fma4(acc, __int_as_float(e.y), u);
    }
    bf[n*64 + i] = acc;
}

// ---- layer2 input transform: h2 = relu(buf1 + b1) @ W2 (R4-proven) ----
__global__ void __launch_bounds__(256) k_xform2(const float* __restrict__ W2, const float* __restrict__ b1){
    __shared__ float sw[256];
    __shared__ float sb[16];
    sw[threadIdx.x] = W2[threadIdx.x];
    if (threadIdx.x < 16) sb[threadIdx.x] = b1[threadIdx.x];
    __syncthreads();
    int r = blockIdx.x*256 + threadIdx.x;
    if (r >= NTOT) return;
    const float4* in = (const float4*)g_buf1 + (size_t)r*4;
    float v[16];
    #pragma unroll
    for (int q=0;q<4;q++){
        float4 t = in[q];
        v[4*q+0]=t.x; v[4*q+1]=t.y; v[4*q+2]=t.z; v[4*q+3]=t.w;
    }
    #pragma unroll
    for (int j=0;j<16;j++) v[j] = fmaxf(v[j] + sb[j], 0.0f);
    float o[16];
    #pragma unroll
    for (int j=0;j<16;j++) o[j] = 0.0f;
    #pragma unroll
    for (int j=0;j<16;j++){
        float vj = v[j];
        #pragma unroll
        for (int jo=0;jo<16;jo++) o[jo] = fmaf(vj, sw[j*16+jo], o[jo]);
    }
    float4* out = (float4*)g_h2 + (size_t)r*4;
    #pragma unroll
    for (int q=0;q<4;q++)
        out[q] = make_float4(o[4*q+0], o[4*q+1], o[4*q+2], o[4*q+3]);
}

// ---- column MLP, parallelized: 16 threads per row (one per hidden j) ----
// grid = BATCH*NCOL*16/256 = 64 blocks. Row r broadcast-reads CF; shfl-reduce over j.
__global__ void __launch_bounds__(256) k_colmlp(const float* __restrict__ CF, const float* __restrict__ cw1,
                                                const float* __restrict__ cb1, const float* __restrict__ cw2,
                                                const float* __restrict__ cb2){
    __shared__ __align__(16) float sw[FCOL*16];    // [k][j]
    __shared__ float sb1[16], sw2[16], scb2;
    for (int i = threadIdx.x; i < FCOL*16/4; i += 256)
        ((float4*)sw)[i] = ((const float4*)cw1)[i];
    if (threadIdx.x < 16){ sb1[threadIdx.x]=cb1[threadIdx.x]; sw2[threadIdx.x]=cw2[threadIdx.x]; }
    if (threadIdx.x == 0) scb2 = cb2[0];
    __syncthreads();
    int gt = blockIdx.x*256 + threadIdx.x;
    int r = gt >> 4;          // row 0..1023
    int j = gt & 15;          // hidden unit
    const float4* xr = (const float4*)CF + (size_t)r*(FCOL/4);
    float acc = sb1[j];
    #pragma unroll 8
    for (int k4 = 0; k4 < FCOL/4; k4++){
        float4 xv = xr[k4];   // broadcast across the 16 j-lanes of this row
        acc = fmaf(xv.x, sw[(k4*4+0)*16 + j], acc);
        acc = fmaf(xv.y, sw[(k4*4+1)*16 + j], acc);
        acc = fmaf(xv.z, sw[(k4*4+2)*16 + j], acc);
        acc = fmaf(xv.w, sw[(k4*4+3)*16 + j], acc);
    }
    float val = fmaxf(acc, 0.0f) * sw2[j];
    val += __shfl_xor_sync(0xffffffffu, val, 1);
    val += __shfl_xor_sync(0xffffffffu, val, 2);
    val += __shfl_xor_sync(0xffffffffu, val, 4);
    val += __shfl_xor_sync(0xffffffffu, val, 8);
    if (j == 0) g_col[r] = val + scb2;
}

// ---- final: node head + broadcast add with col logits (R4-proven) ----
__global__ void __launch_bounds__(256) k_final(const float* __restrict__ b2, const float* __restrict__ fcw,
                                               const float* __restrict__ fcb, float* __restrict__ out){
    __shared__ __align__(16) float scol[BATCH*NCOL];
    __shared__ float sb2[16], sfw[16];
    for (int i = threadIdx.x; i < BATCH*NCOL; i += 256) scol[i] = g_col[i];
    if (threadIdx.x < 16){ sb2[threadIdx.x]=b2[threadIdx.x]; sfw[threadIdx.x]=fcw[threadIdx.x]; }
    __syncthreads();
    int r = blockIdx.x*256 + threadIdx.x;
    if (r >= NTOT) return;
    int b = r / N_NODES, n = r - b*N_NODES;
    const float4* in = (const float4*)g_buf2 + ((size_t)n*16 + b)*4;
    float logit = fcb[0];
    #pragma unroll
    for (int q=0;q<4;q++){
        float4 t = in[q];
        logit = fmaf(fmaxf(t.x + sb2[4*q+0], 0.0f), sfw[4*q+0], logit);
        logit = fmaf(fmaxf(t.y + sb2[4*q+1], 0.0f), sfw[4*q+1], logit);
        logit = fmaf(fmaxf(t.z + sb2[4*q+2], 0.0f), sfw[4*q+2], logit);
        logit = fmaf(fmaxf(t.w + sb2[4*q+3], 0.0f), sfw[4*q+3], logit);
    }
    float4* o = (float4*)out + (size_t)r*16;          // out[b][n*64 + c]
    const float4* sc = (const float4*)scol + b*16;
    #pragma unroll
    for (int c4 = 0; c4 < 16; c4++){
        float4 cv = sc[c4];
        o[c4] = make_float4(logit+cv.x, logit+cv.y, logit+cv.z, logit+cv.w);
    }
}

extern "C" void kernel_launch(void* const* d_in, const int* in_sizes, int n_in,
                              void* d_out, int out_size){
    const float* X   = (const float*)d_in[0];
    const float* CF  = (const float*)d_in[1];
    const int*   ei  = (const int*)d_in[2];
    const float* W1  = (const float*)d_in[3];
    const float* b1  = (const float*)d_in[4];
    const float* W2  = (const float*)d_in[5];
    const float* b2  = (const float*)d_in[6];
    const float* fcw = (const float*)d_in[7];
    const float* fcb = (const float*)d_in[8];
    const float* cw1 = (const float*)d_in[9];
    const float* cb1 = (const float*)d_in[10];
    const float* cw2 = (const float*)d_in[11];
    const float* cb2 = (const float*)d_in[12];
    float* out = (float*)d_out;

    k_count <<<(NEDGE/4+255)/256, 256>>>(ei);
    k_scan  <<<1, 1024>>>();
    k_fill  <<<(NEDGE/2+255)/256, 256>>>(ei);
    k_colmlp<<<(BATCH*NCOL*16)/256, 256>>>(CF, cw1, cb1, cw2, cb2);
    k_gemm1 <<<NTOT/GR, GR>>>(X, W1);
    k_gather<<<(N_NODES*64)/256 + 1, 256>>>(0);
    k_xform2<<<(NTOT+255)/256, 256>>>(W2, b1);
    k_gather<<<(N_NODES*64)/256 + 1, 256>>>(1);
    k_final <<<(NTOT+255)/256, 256>>>(b2, fcw, fcb, out);
}

// round 8
// speedup vs baseline: 1.5196x; 1.0963x over previous
#include <cuda_runtime.h>

#define N_NODES 5000
#define BATCH   16
#define FEAT    512
#define NEDGE   160000
#define NCOL    64
#define FCOL    128
#define NTOT    (N_NODES*BATCH)   // 80000

// Scratch (device globals; zero-initialized at load; no allocation allowed)
__device__ __align__(16) float g_h1  [N_NODES*BATCH*16];
__device__ __align__(16) float g_buf1[N_NODES*BATCH*16];
__device__ __align__(16) float g_h2  [N_NODES*BATCH*16];
__device__ __align__(16) float g_buf2[N_NODES*BATCH*16];
__device__ int   g_deg [N_NODES];          // zero at entry (re-zeroed in k_gemm1 each run)
__device__ int   g_cursor[N_NODES];        // ditto
__device__ int   g_rowstart[N_NODES+1];
__device__ float g_dinv[N_NODES];
__device__ __align__(16) int2 g_csr[NEDGE];   // x = src node, y = norm (float bits)
__device__ float g_col [BATCH*NCOL];

// ---- packed f32x2 helpers (Blackwell) ----
__device__ __forceinline__ unsigned long long splat2(float x){
    unsigned long long r; asm("mov.b64 %0, {%1, %1};" : "=l"(r) : "f"(x)); return r;
}
__device__ __forceinline__ unsigned long long ffma2(unsigned long long a, unsigned long long b, unsigned long long c){
    unsigned long long d; asm("fma.rn.f32x2 %0, %1, %2, %3;" : "=l"(d) : "l"(a), "l"(b), "l"(c)); return d;
}
__device__ __forceinline__ float2 unpack2(unsigned long long v){
    float2 r; asm("mov.b64 {%0, %1}, %2;" : "=f"(r.x), "=f"(r.y) : "l"(v)); return r;
}
__device__ __forceinline__ void fma4(float4& a, float nr, const float4& u){
    a.x = fmaf(nr, u.x, a.x); a.y = fmaf(nr, u.y, a.y);
    a.z = fmaf(nr, u.z, a.z); a.w = fmaf(nr, u.w, a.w);
}

// edge_index is INT32 (proven). Layout [2, E]: src = ei[0..E), dst = ei[E..2E).

// ---- degree count: 4 edges per thread via int4 over the dst half ----
__global__ void k_count(const int* __restrict__ ei){
    int e4 = blockIdx.x*blockDim.x + threadIdx.x;
    if (e4 < NEDGE/4){
        int4 v = ((const int4*)(ei + NEDGE))[e4];
        atomicAdd(&g_deg[v.x], 1);
        atomicAdd(&g_deg[v.y], 1);
        atomicAdd(&g_deg[v.z], 1);
        atomicAdd(&g_deg[v.w], 1);
    }
}
// single-block exclusive scan over 5000 degree counts (+ dinv)
__global__ void __launch_bounds__(1024) k_scan(){
    __shared__ int part[1024];
    int t = threadIdx.x;
    const int CH = (N_NODES + 1023) / 1024;   // 5
    int base = t * CH;
    int s = 0;
    #pragma unroll
    for (int j = 0; j < CH; j++){ int idx = base + j; if (idx < N_NODES) s += g_deg[idx]; }
    part[t] = s; __syncthreads();
    for (int off = 1; off < 1024; off <<= 1){
        int v = (t >= off) ? part[t - off] : 0;
        __syncthreads();
        part[t] += v;
        __syncthreads();
    }
    int excl = (t == 0) ? 0 : part[t - 1];
    #pragma unroll
    for (int j = 0; j < CH; j++){
        int idx = base + j;
        if (idx < N_NODES){
            int d = g_deg[idx];
            g_rowstart[idx] = excl; excl += d;
            g_dinv[idx] = rsqrtf((float)(d + 1));
        }
    }
    if (t == 0) g_rowstart[N_NODES] = NEDGE;
}
// CSR fill: 2 edges per thread via int2 loads
__global__ void k_fill(const int* __restrict__ ei){
    int e2 = blockIdx.x*blockDim.x + threadIdx.x;
    if (e2 >= NEDGE/2) return;
    int2 sp = ((const int2*)ei)[e2];
    int2 dp = ((const int2*)(ei + NEDGE))[e2];
    {
        int pos = atomicAdd(&g_cursor[dp.x], 1);
        g_csr[g_rowstart[dp.x] + pos] = make_int2(sp.x, __float_as_int(g_dinv[sp.x]*g_dinv[dp.x]));
    }
    {
        int pos = atomicAdd(&g_cursor[dp.y], 1);
        g_csr[g_rowstart[dp.y] + pos] = make_int2(sp.y, __float_as_int(g_dinv[sp.y]*g_dinv[dp.y]));
    }
}

// ---- GEMM1: h1[n][b][0:16] = X[b][n][:] @ W1 ----
// Software-pipelined: prefetch chunk c+1 to registers while computing chunk c from smem.
#define GR 128
#define KC 16
#define TSTRIDE 20
__global__ void __launch_bounds__(GR) k_gemm1(const float* __restrict__ X, const float* __restrict__ W1){
    __shared__ __align__(16) float ws[FEAT*16];        // 32 KB
    __shared__ __align__(16) float tile[GR*TSTRIDE];   // 10 KB
    int t = threadIdx.x;
    // re-zero CSR counters for the NEXT run (their last consumer, k_fill, already ran)
    int gid = blockIdx.x*GR + t;
    if (gid < N_NODES){ g_deg[gid] = 0; g_cursor[gid] = 0; }
    for (int i = t; i < FEAT*16/4; i += GR)
        ((float4*)ws)[i] = ((const float4*)W1)[i];
    int row0 = blockIdx.x * GR;                         // 80000 = 625*128, exact
    const float4* Xb = (const float4*)X + (size_t)row0*(FEAT/4);
    // per-thread tile-load coordinates (4 slots)
    int rr[4], kq[4];
    #pragma unroll
    for (int i = 0; i < 4; i++){
        int f = t + GR*i;
        rr[i] = f >> 2; kq[i] = f & 3;
    }
    // preload chunk 0
    float4 pre[4];
    #pragma unroll
    for (int i = 0; i < 4; i++)
        pre[i] = Xb[(size_t)rr[i]*(FEAT/4) + kq[i]];
    unsigned long long acc[8] = {0,0,0,0,0,0,0,0};
    for (int c = 0; c < FEAT/KC; c++){
        __syncthreads();   // previous compute done (and, at c=0, ws loaded)
        #pragma unroll
        for (int i = 0; i < 4; i++)
            *((float4*)&tile[rr[i]*TSTRIDE + kq[i]*4]) = pre[i];
        __syncthreads();
        if (c + 1 < FEAT/KC){
            #pragma unroll
            for (int i = 0; i < 4; i++)
                pre[i] = Xb[(size_t)rr[i]*(FEAT/4) + (c+1)*4 + kq[i]];
        }
        #pragma unroll
        for (int q = 0; q < 4; q++){
            float4 xv = *((const float4*)&tile[t*TSTRIDE + q*4]);
            int kbase = c*KC + q*4;
            #pragma unroll
            for (int kk = 0; kk < 4; kk++){
                float xs = (kk==0)?xv.x:(kk==1)?xv.y:(kk==2)?xv.z:xv.w;
                unsigned long long x2 = splat2(xs);
                const ulonglong2* wk = (const ulonglong2*)&ws[(kbase+kk)*16];
                ulonglong2 w0 = wk[0], w1 = wk[1], w2 = wk[2], w3 = wk[3];
                acc[0]=ffma2(x2,w0.x,acc[0]); acc[1]=ffma2(x2,w0.y,acc[1]);
                acc[2]=ffma2(x2,w1.x,acc[2]); acc[3]=ffma2(x2,w1.y,acc[3]);
                acc[4]=ffma2(x2,w2.x,acc[4]); acc[5]=ffma2(x2,w2.y,acc[5]);
                acc[6]=ffma2(x2,w3.x,acc[6]); acc[7]=ffma2(x2,w3.y,acc[7]);
            }
        }
    }
    int r = row0 + t;
    int b = r / N_NODES, n = r - b*N_NODES;
    float4* dst = (float4*)g_h1 + ((size_t)n*16 + b)*4;
    #pragma unroll
    for (int q = 0; q < 4; q++){
        float2 lo = unpack2(acc[2*q]), hi = unpack2(acc[2*q+1]);
        dst[q] = make_float4(lo.x, lo.y, hi.x, hi.y);
    }
}

// ---- gather: buf[n][*] = dinv[n]^2 * h[n][*] + sum_{e: dst=n} norm_e * h[src_e][*] ----
// 64 threads per node (one float4 lane each), 8-deep unrolled edge loop. (proven)
__global__ void __launch_bounds__(256) k_gather(int layer){
    int gt = blockIdx.x*256 + threadIdx.x;
    int n = gt >> 6;
    int i = gt & 63;
    if (n >= N_NODES) return;
    const float4* __restrict__ h  = (const float4*)(layer ? g_h2  : g_h1);
    float4*       __restrict__ bf = (float4*)      (layer ? g_buf2 : g_buf1);
    float di = g_dinv[n];
    float sl = di * di;
    float4 v = h[n*64 + i];
    float4 acc = make_float4(v.x*sl, v.y*sl, v.z*sl, v.w*sl);
    int k   = g_rowstart[n];
    int end = g_rowstart[n+1];
    for (; k + 8 <= end; k += 8){
        int2 e0 = g_csr[k+0], e1 = g_csr[k+1], e2 = g_csr[k+2], e3 = g_csr[k+3];
        int2 e4 = g_csr[k+4], e5 = g_csr[k+5], e6 = g_csr[k+6], e7 = g_csr[k+7];
        float4 u0 = h[e0.x*64 + i], u1 = h[e1.x*64 + i], u2 = h[e2.x*64 + i], u3 = h[e3.x*64 + i];
        float4 u4 = h[e4.x*64 + i], u5 = h[e5.x*64 + i], u6 = h[e6.x*64 + i], u7 = h[e7.x*64 + i];
        fma4(acc, __int_as_float(e0.y), u0); fma4(acc, __int_as_float(e1.y), u1);
        fma4(acc, __int_as_float(e2.y), u2); fma4(acc, __int_as_float(e3.y), u3);
        fma4(acc, __int_as_float(e4.y), u4); fma4(acc, __int_as_float(e5.y), u5);
        fma4(acc, __int_as_float(e6.y), u6); fma4(acc, __int_as_float(e7.y), u7);
    }
    for (; k + 4 <= end; k += 4){
        int2 e0 = g_csr[k+0], e1 = g_csr[k+1], e2 = g_csr[k+2], e3 = g_csr[k+3];
        float4 u0 = h[e0.x*64 + i], u1 = h[e1.x*64 + i], u2 = h[e2.x*64 + i], u3 = h[e3.x*64 + i];
        fma4(acc, __int_as_float(e0.y), u0); fma4(acc, __int_as_float(e1.y), u1);
        fma4(acc, __int_as_float(e2.y), u2); fma4(acc, __int_as_float(e3.y), u3);
    }
    for (; k < end; k++){
        int2 e = g_csr[k];
        float4 u = h[e.x*64 + i];
        fma4(acc, __int_as_float(e.y), u);
    }
    bf[n*64 + i] = acc;
}

// ---- layer2 input transform: h2 = relu(buf1 + b1) @ W2 (proven) ----
__global__ void __launch_bounds__(256) k_xform2(const float* __restrict__ W2, const float* __restrict__ b1){
    __shared__ float sw[256];
    __shared__ float sb[16];
    sw[threadIdx.x] = W2[threadIdx.x];
    if (threadIdx.x < 16) sb[threadIdx.x] = b1[threadIdx.x];
    __syncthreads();
    int r = blockIdx.x*256 + threadIdx.x;
    if (r >= NTOT) return;
    const float4* in = (const float4*)g_buf1 + (size_t)r*4;
    float v[16];
    #pragma unroll
    for (int q=0;q<4;q++){
        float4 t = in[q];
        v[4*q+0]=t.x; v[4*q+1]=t.y; v[4*q+2]=t.z; v[4*q+3]=t.w;
    }
    #pragma unroll
    for (int j=0;j<16;j++) v[j] = fmaxf(v[j] + sb[j], 0.0f);
    float o[16];
    #pragma unroll
    for (int j=0;j<16;j++) o[j] = 0.0f;
    #pragma unroll
    for (int j=0;j<16;j++){
        float vj = v[j];
        #pragma unroll
        for (int jo=0;jo<16;jo++) o[jo] = fmaf(vj, sw[j*16+jo], o[jo]);
    }
    float4* out = (float4*)g_h2 + (size_t)r*4;
    #pragma unroll
    for (int q=0;q<4;q++)
        out[q] = make_float4(o[4*q+0], o[4*q+1], o[4*q+2], o[4*q+3]);
}

// ---- column MLP, parallelized: 16 threads per row (one per hidden j) ----
__global__ void __launch_bounds__(256) k_colmlp(const float* __restrict__ CF, const float* __restrict__ cw1,
                                                const float* __restrict__ cb1, const float* __restrict__ cw2,
                                                const float* __restrict__ cb2){
    __shared__ __align__(16) float sw[FCOL*16];    // [k][j]
    __shared__ float sb1[16], sw2[16], scb2;
    for (int i = threadIdx.x; i < FCOL*16/4; i += 256)
        ((float4*)sw)[i] = ((const float4*)cw1)[i];
    if (threadIdx.x < 16){ sb1[threadIdx.x]=cb1[threadIdx.x]; sw2[threadIdx.x]=cw2[threadIdx.x]; }
    if (threadIdx.x == 0) scb2 = cb2[0];
    __syncthreads();
    int gt = blockIdx.x*256 + threadIdx.x;
    int r = gt >> 4;          // row 0..1023
    int j = gt & 15;          // hidden unit
    const float4* xr = (const float4*)CF + (size_t)r*(FCOL/4);
    float acc = sb1[j];
    #pragma unroll 8
    for (int k4 = 0; k4 < FCOL/4; k4++){
        float4 xv = xr[k4];
        acc = fmaf(xv.x, sw[(k4*4+0)*16 + j], acc);
        acc = fmaf(xv.y, sw[(k4*4+1)*16 + j], acc);
        acc = fmaf(xv.z, sw[(k4*4+2)*16 + j], acc);
        acc = fmaf(xv.w, sw[(k4*4+3)*16 + j], acc);
    }
    float val = fmaxf(acc, 0.0f) * sw2[j];
    val += __shfl_xor_sync(0xffffffffu, val, 1);
    val += __shfl_xor_sync(0xffffffffu, val, 2);
    val += __shfl_xor_sync(0xffffffffu, val, 4);
    val += __shfl_xor_sync(0xffffffffu, val, 8);
    if (j == 0) g_col[r] = val + scb2;
}

// ---- final: node head + broadcast add with col logits (proven) ----
__global__ void __launch_bounds__(256) k_final(const float* __restrict__ b2, const float* __restrict__ fcw,
                                               const float* __restrict__ fcb, float* __restrict__ out){
    __shared__ __align__(16) float scol[BATCH*NCOL];
    __shared__ float sb2[16], sfw[16];
    for (int i = threadIdx.x; i < BATCH*NCOL; i += 256) scol[i] = g_col[i];
    if (threadIdx.x < 16){ sb2[threadIdx.x]=b2[threadIdx.x]; sfw[threadIdx.x]=fcw[threadIdx.x]; }
    __syncthreads();
    int r = blockIdx.x*256 + threadIdx.x;
    if (r >= NTOT) return;
    int b = r / N_NODES, n = r - b*N_NODES;
    const float4* in = (const float4*)g_buf2 + ((size_t)n*16 + b)*4;
    float logit = fcb[0];
    #pragma unroll
    for (int q=0;q<4;q++){
        float4 t = in[q];
        logit = fmaf(fmaxf(t.x + sb2[4*q+0], 0.0f), sfw[4*q+0], logit);
        logit = fmaf(fmaxf(t.y + sb2[4*q+1], 0.0f), sfw[4*q+1], logit);
        logit = fmaf(fmaxf(t.z + sb2[4*q+2], 0.0f), sfw[4*q+2], logit);
        logit = fmaf(fmaxf(t.w + sb2[4*q+3], 0.0f), sfw[4*q+3], logit);
    }
    float4* o = (float4*)out + (size_t)r*16;          // out[b][n*64 + c]
    const float4* sc = (const float4*)scol + b*16;
    #pragma unroll
    for (int c4 = 0; c4 < 16; c4++){
        float4 cv = sc[c4];
        o[c4] = make_float4(logit+cv.x, logit+cv.y, logit+cv.z, logit+cv.w);
    }
}

extern "C" void kernel_launch(void* const* d_in, const int* in_sizes, int n_in,
                              void* d_out, int out_size){
    const float* X   = (const float*)d_in[0];
    const float* CF  = (const float*)d_in[1];
    const int*   ei  = (const int*)d_in[2];
    const float* W1  = (const float*)d_in[3];
    const float* b1  = (const float*)d_in[4];
    const float* W2  = (const float*)d_in[5];
    const float* b2  = (const float*)d_in[6];
    const float* fcw = (const float*)d_in[7];
    const float* fcb = (const float*)d_in[8];
    const float* cw1 = (const float*)d_in[9];
    const float* cb1 = (const float*)d_in[10];
    const float* cw2 = (const float*)d_in[11];
    const float* cb2 = (const float*)d_in[12];
    float* out = (float*)d_out;

    // k_gemm1 is launch #4 — the profiler captures it this round.
    k_count <<<(NEDGE/4+255)/256, 256>>>(ei);
    k_scan  <<<1, 1024>>>();
    k_fill  <<<(NEDGE/2+255)/256, 256>>>(ei);
    k_gemm1 <<<NTOT/GR, GR>>>(X, W1);
    k_gather<<<(N_NODES*64)/256 + 1, 256>>>(0);
    k_xform2<<<(NTOT+255)/256, 256>>>(W2, b1);
    k_gather<<<(N_NODES*64)/256 + 1, 256>>>(1);
    k_colmlp<<<(BATCH*NCOL*16)/256, 256>>>(CF, cw1, cb1, cw2, cb2);
    k_final <<<(NTOT+255)/256, 256>>>(b2, fcw, fcb, out);
}

// round 9
// speedup vs baseline: 1.6484x; 1.0848x over previous
#include <cuda_runtime.h>

#define N_NODES 5000
#define BATCH   16
#define FEAT    512
#define NEDGE   160000
#define NCOL    64
#define FCOL    128
#define NTOT    (N_NODES*BATCH)   // 80000

// Scratch (device globals; zero-initialized at load; no allocation allowed)
__device__ __align__(16) float g_h1  [N_NODES*BATCH*16];
__device__ __align__(16) float g_buf1[N_NODES*BATCH*16];   // also k_gemm1 partial (kh=0), row-major [r][16]
__device__ __align__(16) float g_h2  [N_NODES*BATCH*16];
__device__ __align__(16) float g_buf2[N_NODES*BATCH*16];   // also k_gemm1 partial (kh=1)
__device__ int   g_deg [N_NODES];          // zero at entry (re-zeroed in k_gemm1 each run)
__device__ int   g_cursor[N_NODES];        // ditto
__device__ int   g_rowstart[N_NODES+1];
__device__ float g_dinv[N_NODES];
__device__ __align__(16) int2 g_csr[NEDGE];   // x = src node, y = norm (float bits)
__device__ float g_col [BATCH*NCOL];

// ---- packed f32x2 helpers (Blackwell) ----
__device__ __forceinline__ unsigned long long splat2(float x){
    unsigned long long r; asm("mov.b64 %0, {%1, %1};" : "=l"(r) : "f"(x)); return r;
}
__device__ __forceinline__ unsigned long long ffma2(unsigned long long a, unsigned long long b, unsigned long long c){
    unsigned long long d; asm("fma.rn.f32x2 %0, %1, %2, %3;" : "=l"(d) : "l"(a), "l"(b), "l"(c)); return d;
}
__device__ __forceinline__ float2 unpack2(unsigned long long v){
    float2 r; asm("mov.b64 {%0, %1}, %2;" : "=f"(r.x), "=f"(r.y) : "l"(v)); return r;
}
__device__ __forceinline__ void fma4(float4& a, float nr, const float4& u){
    a.x = fmaf(nr, u.x, a.x); a.y = fmaf(nr, u.y, a.y);
    a.z = fmaf(nr, u.z, a.z); a.w = fmaf(nr, u.w, a.w);
}

// edge_index is INT32 (proven). Layout [2, E]: src = ei[0..E), dst = ei[E..2E).

// ---- degree count: 4 edges per thread via int4 over the dst half ----
__global__ void k_count(const int* __restrict__ ei){
    int e4 = blockIdx.x*blockDim.x + threadIdx.x;
    if (e4 < NEDGE/4){
        int4 v = ((const int4*)(ei + NEDGE))[e4];
        atomicAdd(&g_deg[v.x], 1);
        atomicAdd(&g_deg[v.y], 1);
        atomicAdd(&g_deg[v.z], 1);
        atomicAdd(&g_deg[v.w], 1);
    }
}
// single-block exclusive scan over 5000 degree counts (+ dinv)
__global__ void __launch_bounds__(1024) k_scan(){
    __shared__ int part[1024];
    int t = threadIdx.x;
    const int CH = (N_NODES + 1023) / 1024;   // 5
    int base = t * CH;
    int s = 0;
    #pragma unroll
    for (int j = 0; j < CH; j++){ int idx = base + j; if (idx < N_NODES) s += g_deg[idx]; }
    part[t] = s; __syncthreads();
    for (int off = 1; off < 1024; off <<= 1){
        int v = (t >= off) ? part[t - off] : 0;
        __syncthreads();
        part[t] += v;
        __syncthreads();
    }
    int excl = (t == 0) ? 0 : part[t - 1];
    #pragma unroll
    for (int j = 0; j < CH; j++){
        int idx = base + j;
        if (idx < N_NODES){
            int d = g_deg[idx];
            g_rowstart[idx] = excl; excl += d;
            g_dinv[idx] = rsqrtf((float)(d + 1));
        }
    }
    if (t == 0) g_rowstart[N_NODES] = NEDGE;
}
// CSR fill: 2 edges per thread via int2 loads
__global__ void k_fill(const int* __restrict__ ei){
    int e2 = blockIdx.x*blockDim.x + threadIdx.x;
    if (e2 >= NEDGE/2) return;
    int2 sp = ((const int2*)ei)[e2];
    int2 dp = ((const int2*)(ei + NEDGE))[e2];
    {
        int pos = atomicAdd(&g_cursor[dp.x], 1);
        g_csr[g_rowstart[dp.x] + pos] = make_int2(sp.x, __float_as_int(g_dinv[sp.x]*g_dinv[dp.x]));
    }
    {
        int pos = atomicAdd(&g_cursor[dp.y], 1);
        g_csr[g_rowstart[dp.y] + pos] = make_int2(sp.y, __float_as_int(g_dinv[sp.y]*g_dinv[dp.y]));
    }
}

// ---- GEMM1 split-K2: partial[kh][r][16] = X[r][kh*256:(kh+1)*256] @ W1[kh half] ----
// grid (625, 2); block 128. smem 26KB -> ~6 blocks/SM; double warps vs R8.
#define GR 128
#define KC 16
#define KHALF 256
#define TSTRIDE 20
__global__ void __launch_bounds__(GR, 6) k_gemm1(const float* __restrict__ X, const float* __restrict__ W1){
    __shared__ __align__(16) float ws[KHALF*16];       // 16 KB (this k-half of W)
    __shared__ __align__(16) float tile[GR*TSTRIDE];   // 10 KB
    int t  = threadIdx.x;
    int kh = blockIdx.y;
    // re-zero CSR counters for the NEXT run (their last consumer, k_fill, already ran)
    if (kh == 0){
        int gid = blockIdx.x*GR + t;
        if (gid < N_NODES){ g_deg[gid] = 0; g_cursor[gid] = 0; }
    }
    const float4* W14 = (const float4*)W1 + kh*(KHALF*16/4);
    for (int i = t; i < KHALF*16/4; i += GR)
        ((float4*)ws)[i] = W14[i];
    int row0 = blockIdx.x * GR;                         // 80000 = 625*128, exact
    const float4* Xb = (const float4*)X + (size_t)row0*(FEAT/4) + kh*(KHALF/4);
    int rr[4], kq[4];
    #pragma unroll
    for (int i = 0; i < 4; i++){
        int f = t + GR*i;
        rr[i] = f >> 2; kq[i] = f & 3;
    }
    float4 pre[4];
    #pragma unroll
    for (int i = 0; i < 4; i++)
        pre[i] = Xb[(size_t)rr[i]*(FEAT/4) + kq[i]];
    unsigned long long acc[8] = {0,0,0,0,0,0,0,0};
    for (int c = 0; c < KHALF/KC; c++){                 // 16 chunks
        __syncthreads();
        #pragma unroll
        for (int i = 0; i < 4; i++)
            *((float4*)&tile[rr[i]*TSTRIDE + kq[i]*4]) = pre[i];
        __syncthreads();
        if (c + 1 < KHALF/KC){
            #pragma unroll
            for (int i = 0; i < 4; i++)
                pre[i] = Xb[(size_t)rr[i]*(FEAT/4) + (c+1)*4 + kq[i]];
        }
        #pragma unroll
        for (int q = 0; q < 4; q++){
            float4 xv = *((const float4*)&tile[t*TSTRIDE + q*4]);
            int kbase = c*KC + q*4;
            #pragma unroll
            for (int kk = 0; kk < 4; kk++){
                float xs = (kk==0)?xv.x:(kk==1)?xv.y:(kk==2)?xv.z:xv.w;
                unsigned long long x2 = splat2(xs);
                const ulonglong2* wk = (const ulonglong2*)&ws[(kbase+kk)*16];
                ulonglong2 w0 = wk[0], w1 = wk[1], w2 = wk[2], w3 = wk[3];
                acc[0]=ffma2(x2,w0.x,acc[0]); acc[1]=ffma2(x2,w0.y,acc[1]);
                acc[2]=ffma2(x2,w1.x,acc[2]); acc[3]=ffma2(x2,w1.y,acc[3]);
                acc[4]=ffma2(x2,w2.x,acc[4]); acc[5]=ffma2(x2,w2.y,acc[5]);
                acc[6]=ffma2(x2,w3.x,acc[6]); acc[7]=ffma2(x2,w3.y,acc[7]);
            }
        }
    }
    // partial out, row-major [r][16]
    float4* dst = (float4*)(kh ? g_buf2 : g_buf1) + (size_t)(row0 + t)*4;
    #pragma unroll
    for (int q = 0; q < 4; q++){
        float2 lo = unpack2(acc[2*q]), hi = unpack2(acc[2*q+1]);
        dst[q] = make_float4(lo.x, lo.y, hi.x, hi.y);
    }
}

// ---- reduce split-K partials + transpose to [n][b][16] layout ----
__global__ void k_red(){
    int i = blockIdx.x*256 + threadIdx.x;              // < NTOT*4 = 320000 float4s
    if (i >= NTOT*4) return;
    float4 a = ((const float4*)g_buf1)[i];
    float4 c = ((const float4*)g_buf2)[i];
    int r = i >> 2, q = i & 3;
    int b = r / N_NODES, n = r - b*N_NODES;
    ((float4*)g_h1)[(n*16 + b)*4 + q] = make_float4(a.x+c.x, a.y+c.y, a.z+c.z, a.w+c.w);
}

// ---- gather: buf[n][*] = dinv[n]^2 * h[n][*] + sum_{e: dst=n} norm_e * h[src_e][*] ----
// 64 threads per node (one float4 lane each), 8-deep unrolled edge loop. (proven)
__global__ void __launch_bounds__(256) k_gather(int layer){
    int gt = blockIdx.x*256 + threadIdx.x;
    int n = gt >> 6;
    int i = gt & 63;
    if (n >= N_NODES) return;
    const float4* __restrict__ h  = (const float4*)(layer ? g_h2  : g_h1);
    float4*       __restrict__ bf = (float4*)      (layer ? g_buf2 : g_buf1);
    float di = g_dinv[n];
    float sl = di * di;
    float4 v = h[n*64 + i];
    float4 acc = make_float4(v.x*sl, v.y*sl, v.z*sl, v.w*sl);
    int k   = g_rowstart[n];
    int end = g_rowstart[n+1];
    for (; k + 8 <= end; k += 8){
        int2 e0 = g_csr[k+0], e1 = g_csr[k+1], e2 = g_csr[k+2], e3 = g_csr[k+3];
        int2 e4 = g_csr[k+4], e5 = g_csr[k+5], e6 = g_csr[k+6], e7 = g_csr[k+7];
        float4 u0 = h[e0.x*64 + i], u1 = h[e1.x*64 + i], u2 = h[e2.x*64 + i], u3 = h[e3.x*64 + i];
        float4 u4 = h[e4.x*64 + i], u5 = h[e5.x*64 + i], u6 = h[e6.x*64 + i], u7 = h[e7.x*64 + i];
        fma4(acc, __int_as_float(e0.y), u0); fma4(acc, __int_as_float(e1.y), u1);
        fma4(acc, __int_as_float(e2.y), u2); fma4(acc, __int_as_float(e3.y), u3);
        fma4(acc, __int_as_float(e4.y), u4); fma4(acc, __int_as_float(e5.y), u5);
        fma4(acc, __int_as_float(e6.y), u6); fma4(acc, __int_as_float(e7.y), u7);
    }
    for (; k + 4 <= end; k += 4){
        int2 e0 = g_csr[k+0], e1 = g_csr[k+1], e2 = g_csr[k+2], e3 = g_csr[k+3];
        float4 u0 = h[e0.x*64 + i], u1 = h[e1.x*64 + i], u2 = h[e2.x*64 + i], u3 = h[e3.x*64 + i];
        fma4(acc, __int_as_float(e0.y), u0); fma4(acc, __int_as_float(e1.y), u1);
        fma4(acc, __int_as_float(e2.y), u2); fma4(acc, __int_as_float(e3.y), u3);
    }
    for (; k < end; k++){
        int2 e = g_csr[k];
        float4 u = h[e.x*64 + i];
        fma4(acc, __int_as_float(e.y), u);
    }
    bf[n*64 + i] = acc;
}

// ---- layer2 input transform: h2 = relu(buf1 + b1) @ W2 (proven) ----
__global__ void __launch_bounds__(256) k_xform2(const float* __restrict__ W2, const float* __restrict__ b1){
    __shared__ float sw[256];
    __shared__ float sb[16];
    sw[threadIdx.x] = W2[threadIdx.x];
    if (threadIdx.x < 16) sb[threadIdx.x] = b1[threadIdx.x];
    __syncthreads();
    int r = blockIdx.x*256 + threadIdx.x;
    if (r >= NTOT) return;
    const float4* in = (const float4*)g_buf1 + (size_t)r*4;
    float v[16];
    #pragma unroll
    for (int q=0;q<4;q++){
        float4 t = in[q];
        v[4*q+0]=t.x; v[4*q+1]=t.y; v[4*q+2]=t.z; v[4*q+3]=t.w;
    }
    #pragma unroll
    for (int j=0;j<16;j++) v[j] = fmaxf(v[j] + sb[j], 0.0f);
    float o[16];
    #pragma unroll
    for (int j=0;j<16;j++) o[j] = 0.0f;
    #pragma unroll
    for (int j=0;j<16;j++){
        float vj = v[j];
        #pragma unroll
        for (int jo=0;jo<16;jo++) o[jo] = fmaf(vj, sw[j*16+jo], o[jo]);
    }
    float4* out = (float4*)g_h2 + (size_t)r*4;
    #pragma unroll
    for (int q=0;q<4;q++)
        out[q] = make_float4(o[4*q+0], o[4*q+1], o[4*q+2], o[4*q+3]);
}

// ---- column MLP, parallelized: 16 threads per row (proven) ----
__global__ void __launch_bounds__(256) k_colmlp(const float* __restrict__ CF, const float* __restrict__ cw1,
                                                const float* __restrict__ cb1, const float* __restrict__ cw2,
                                                const float* __restrict__ cb2){
    __shared__ __align__(16) float sw[FCOL*16];    // [k][j]
    __shared__ float sb1[16], sw2[16], scb2;
    for (int i = threadIdx.x; i < FCOL*16/4; i += 256)
        ((float4*)sw)[i] = ((const float4*)cw1)[i];
    if (threadIdx.x < 16){ sb1[threadIdx.x]=cb1[threadIdx.x]; sw2[threadIdx.x]=cw2[threadIdx.x]; }
    if (threadIdx.x == 0) scb2 = cb2[0];
    __syncthreads();
    int gt = blockIdx.x*256 + threadIdx.x;
    int r = gt >> 4;          // row 0..1023
    int j = gt & 15;          // hidden unit
    const float4* xr = (const float4*)CF + (size_t)r*(FCOL/4);
    float acc = sb1[j];
    #pragma unroll 8
    for (int k4 = 0; k4 < FCOL/4; k4++){
        float4 xv = xr[k4];
        acc = fmaf(xv.x, sw[(k4*4+0)*16 + j], acc);
        acc = fmaf(xv.y, sw[(k4*4+1)*16 + j], acc);
        acc = fmaf(xv.z, sw[(k4*4+2)*16 + j], acc);
        acc = fmaf(xv.w, sw[(k4*4+3)*16 + j], acc);
    }
    float val = fmaxf(acc, 0.0f) * sw2[j];
    val += __shfl_xor_sync(0xffffffffu, val, 1);
    val += __shfl_xor_sync(0xffffffffu, val, 2);
    val += __shfl_xor_sync(0xffffffffu, val, 4);
    val += __shfl_xor_sync(0xffffffffu, val, 8);
    if (j == 0) g_col[r] = val + scb2;
}

// ---- final: node head + broadcast add with col logits (proven) ----
__global__ void __launch_bounds__(256) k_final(const float* __restrict__ b2, const float* __restrict__ fcw,
                                               const float* __restrict__ fcb, float* __restrict__ out){
    __shared__ __align__(16) float scol[BATCH*NCOL];
    __shared__ float sb2[16], sfw[16];
    for (int i = threadIdx.x; i < BATCH*NCOL; i += 256) scol[i] = g_col[i];
    if (threadIdx.x < 16){ sb2[threadIdx.x]=b2[threadIdx.x]; sfw[threadIdx.x]=fcw[threadIdx.x]; }
    __syncthreads();
    int r = blockIdx.x*256 + threadIdx.x;
    if (r >= NTOT) return;
    int b = r / N_NODES, n = r - b*N_NODES;
    const float4* in = (const float4*)g_buf2 + ((size_t)n*16 + b)*4;
    float logit = fcb[0];
    #pragma unroll
    for (int q=0;q<4;q++){
        float4 t = in[q];
        logit = fmaf(fmaxf(t.x + sb2[4*q+0], 0.0f), sfw[4*q+0], logit);
        logit = fmaf(fmaxf(t.y + sb2[4*q+1], 0.0f), sfw[4*q+1], logit);
        logit = fmaf(fmaxf(t.z + sb2[4*q+2], 0.0f), sfw[4*q+2], logit);
        logit = fmaf(fmaxf(t.w + sb2[4*q+3], 0.0f), sfw[4*q+3], logit);
    }
    float4* o = (float4*)out + (size_t)r*16;          // out[b][n*64 + c]
    const float4* sc = (const float4*)scol + b*16;
    #pragma unroll
    for (int c4 = 0; c4 < 16; c4++){
        float4 cv = sc[c4];
        o[c4] = make_float4(logit+cv.x, logit+cv.y, logit+cv.z, logit+cv.w);
    }
}

extern "C" void kernel_launch(void* const* d_in, const int* in_sizes, int n_in,
                              void* d_out, int out_size){
    const float* X   = (const float*)d_in[0];
    const float* CF  = (const float*)d_in[1];
    const int*   ei  = (const int*)d_in[2];
    const float* W1  = (const float*)d_in[3];
    const float* b1  = (const float*)d_in[4];
    const float* W2  = (const float*)d_in[5];
    const float* b2  = (const float*)d_in[6];
    const float* fcw = (const float*)d_in[7];
    const float* fcb = (const float*)d_in[8];
    const float* cw1 = (const float*)d_in[9];
    const float* cb1 = (const float*)d_in[10];
    const float* cw2 = (const float*)d_in[11];
    const float* cb2 = (const float*)d_in[12];
    float* out = (float*)d_out;

    // k_gemm1 is launch #4 — profiled next round.
    k_count <<<(NEDGE/4+255)/256, 256>>>(ei);
    k_scan  <<<1, 1024>>>();
    k_fill  <<<(NEDGE/2+255)/256, 256>>>(ei);
    k_gemm1 <<<dim3(NTOT/GR, 2), GR>>>(X, W1);
    k_red   <<<(NTOT*4+255)/256, 256>>>();
    k_gather<<<(N_NODES*64)/256 + 1, 256>>>(0);
    k_xform2<<<(NTOT+255)/256, 256>>>(W2, b1);
    k_gather<<<(N_NODES*64)/256 + 1, 256>>>(1);
    k_colmlp<<<(BATCH*NCOL*16)/256, 256>>>(CF, cw1, cb1, cw2, cb2);
    k_final <<<(NTOT+255)/256, 256>>>(b2, fcw, fcb, out);
}

// round 10
// speedup vs baseline: 1.8774x; 1.1389x over previous
#include <cuda_runtime.h>
#include <cstdint>

#define N_NODES 5000
#define BATCH   16
#define FEAT    512
#define NEDGE   160000
#define NCOL    64
#define FCOL    128
#define NTOT    (N_NODES*BATCH)   // 80000

// Scratch (device globals; zero-initialized at load; no allocation allowed)
__device__ __align__(16) float g_h1  [N_NODES*BATCH*16];
__device__ __align__(16) float g_buf1[N_NODES*BATCH*16];
__device__ __align__(16) float g_h2  [N_NODES*BATCH*16];
__device__ __align__(16) float g_buf2[N_NODES*BATCH*16];
__device__ __align__(16) float g_part[4*N_NODES*BATCH*16];  // split-K4 partials, [kh][r][16]
__device__ int   g_deg [N_NODES];          // zero at entry (re-zeroed in k_gemm1 each run)
__device__ int   g_cursor[N_NODES];        // ditto
__device__ int   g_rowstart[N_NODES+1];
__device__ float g_dinv[N_NODES];
__device__ __align__(16) int2 g_csr[NEDGE];   // x = src node, y = norm (float bits)
__device__ float g_col [BATCH*NCOL];

// ---- packed f32x2 helpers (Blackwell) ----
__device__ __forceinline__ unsigned long long splat2(float x){
    unsigned long long r; asm("mov.b64 %0, {%1, %1};" : "=l"(r) : "f"(x)); return r;
}
__device__ __forceinline__ unsigned long long ffma2(unsigned long long a, unsigned long long b, unsigned long long c){
    unsigned long long d; asm("fma.rn.f32x2 %0, %1, %2, %3;" : "=l"(d) : "l"(a), "l"(b), "l"(c)); return d;
}
__device__ __forceinline__ float2 unpack2(unsigned long long v){
    float2 r; asm("mov.b64 {%0, %1}, %2;" : "=f"(r.x), "=f"(r.y) : "l"(v)); return r;
}
__device__ __forceinline__ void fma4(float4& a, float nr, const float4& u){
    a.x = fmaf(nr, u.x, a.x); a.y = fmaf(nr, u.y, a.y);
    a.z = fmaf(nr, u.z, a.z); a.w = fmaf(nr, u.w, a.w);
}
__device__ __forceinline__ void cpasync16(uint32_t saddr, const void* gptr){
    asm volatile("cp.async.cg.shared.global [%0], [%1], 16;" :: "r"(saddr), "l"(gptr));
}

// edge_index is INT32 (proven). Layout [2, E]: src = ei[0..E), dst = ei[E..2E).

// ---- degree count: 4 edges per thread via int4 over the dst half ----
__global__ void k_count(const int* __restrict__ ei){
    int e4 = blockIdx.x*blockDim.x + threadIdx.x;
    if (e4 < NEDGE/4){
        int4 v = ((const int4*)(ei + NEDGE))[e4];
        atomicAdd(&g_deg[v.x], 1);
        atomicAdd(&g_deg[v.y], 1);
        atomicAdd(&g_deg[v.z], 1);
        atomicAdd(&g_deg[v.w], 1);
    }
}
// single-block exclusive scan over 5000 degree counts (+ dinv)
__global__ void __launch_bounds__(1024) k_scan(){
    __shared__ int part[1024];
    int t = threadIdx.x;
    const int CH = (N_NODES + 1023) / 1024;   // 5
    int base = t * CH;
    int s = 0;
    #pragma unroll
    for (int j = 0; j < CH; j++){ int idx = base + j; if (idx < N_NODES) s += g_deg[idx]; }
    part[t] = s; __syncthreads();
    for (int off = 1; off < 1024; off <<= 1){
        int v = (t >= off) ? part[t - off] : 0;
        __syncthreads();
        part[t] += v;
        __syncthreads();
    }
    int excl = (t == 0) ? 0 : part[t - 1];
    #pragma unroll
    for (int j = 0; j < CH; j++){
        int idx = base + j;
        if (idx < N_NODES){
            int d = g_deg[idx];
            g_rowstart[idx] = excl; excl += d;
            g_dinv[idx] = rsqrtf((float)(d + 1));
        }
    }
    if (t == 0) g_rowstart[N_NODES] = NEDGE;
}
// CSR fill: 2 edges per thread via int2 loads
__global__ void k_fill(const int* __restrict__ ei){
    int e2 = blockIdx.x*blockDim.x + threadIdx.x;
    if (e2 >= NEDGE/2) return;
    int2 sp = ((const int2*)ei)[e2];
    int2 dp = ((const int2*)(ei + NEDGE))[e2];
    {
        int pos = atomicAdd(&g_cursor[dp.x], 1);
        g_csr[g_rowstart[dp.x] + pos] = make_int2(sp.x, __float_as_int(g_dinv[sp.x]*g_dinv[dp.x]));
    }
    {
        int pos = atomicAdd(&g_cursor[dp.y], 1);
        g_csr[g_rowstart[dp.y] + pos] = make_int2(sp.y, __float_as_int(g_dinv[sp.y]*g_dinv[dp.y]));
    }
}

// ---- GEMM1 split-K4 + cp.async double buffer ----
// grid (625, 4); block 128. smem: W 8KB + 2x10KB tile = 28KB. Target 8 blocks/SM.
#define GR 128
#define KC 16
#define KSPLIT 4
#define KQ (FEAT/KSPLIT)        // 128
#define CHUNKS (KQ/KC)          // 8
#define TSTRIDE 20
__global__ void __launch_bounds__(GR, 8) k_gemm1(const float* __restrict__ X, const float* __restrict__ W1){
    __shared__ __align__(16) float ws[KQ*16];               // 8 KB (this k-quarter of W)
    __shared__ __align__(16) float tile[2][GR*TSTRIDE];     // 2 x 10 KB
    int t  = threadIdx.x;
    int kh = blockIdx.y;
    if (kh == 0){
        int gid = blockIdx.x*GR + t;
        if (gid < N_NODES){ g_deg[gid] = 0; g_cursor[gid] = 0; }
    }
    const float4* W14 = (const float4*)W1 + kh*(KQ*16/4);
    for (int i = t; i < KQ*16/4; i += GR)
        ((float4*)ws)[i] = W14[i];
    int row0 = blockIdx.x * GR;                             // 80000 = 625*128, exact
    const float4* Xb = (const float4*)X + (size_t)row0*(FEAT/4) + kh*(KQ/4);
    // per-thread tile-load coordinates (4 slots)
    int rr[4], kq[4];
    #pragma unroll
    for (int i = 0; i < 4; i++){
        int f = t + GR*i;
        rr[i] = f >> 2; kq[i] = f & 3;
    }
    uint32_t tb[2];
    tb[0] = (uint32_t)__cvta_generic_to_shared(&tile[0][0]);
    tb[1] = (uint32_t)__cvta_generic_to_shared(&tile[1][0]);
    // prologue: chunk 0 -> buf 0
    #pragma unroll
    for (int i = 0; i < 4; i++)
        cpasync16(tb[0] + (rr[i]*TSTRIDE + kq[i]*4)*4, Xb + (size_t)rr[i]*(FEAT/4) + kq[i]);
    asm volatile("cp.async.commit_group;" ::: "memory");
    unsigned long long acc[8] = {0,0,0,0,0,0,0,0};
    for (int c = 0; c < CHUNKS; c++){
        if (c + 1 < CHUNKS){
            uint32_t dstb = tb[(c+1)&1];
            #pragma unroll
            for (int i = 0; i < 4; i++)
                cpasync16(dstb + (rr[i]*TSTRIDE + kq[i]*4)*4,
                          Xb + (size_t)rr[i]*(FEAT/4) + (c+1)*4 + kq[i]);
            asm volatile("cp.async.commit_group;" ::: "memory");
            asm volatile("cp.async.wait_group 1;" ::: "memory");
        } else {
            asm volatile("cp.async.wait_group 0;" ::: "memory");
        }
        __syncthreads();
        const float* tl = &tile[c&1][0];
        #pragma unroll
        for (int q = 0; q < 4; q++){
            float4 xv = *((const float4*)&tl[t*TSTRIDE + q*4]);
            int kbase = c*KC + q*4;
            #pragma unroll
            for (int kk = 0; kk < 4; kk++){
                float xs = (kk==0)?xv.x:(kk==1)?xv.y:(kk==2)?xv.z:xv.w;
                unsigned long long x2 = splat2(xs);
                const ulonglong2* wk = (const ulonglong2*)&ws[(kbase+kk)*16];
                ulonglong2 w0 = wk[0], w1 = wk[1], w2 = wk[2], w3 = wk[3];
                acc[0]=ffma2(x2,w0.x,acc[0]); acc[1]=ffma2(x2,w0.y,acc[1]);
                acc[2]=ffma2(x2,w1.x,acc[2]); acc[3]=ffma2(x2,w1.y,acc[3]);
                acc[4]=ffma2(x2,w2.x,acc[4]); acc[5]=ffma2(x2,w2.y,acc[5]);
                acc[6]=ffma2(x2,w3.x,acc[6]); acc[7]=ffma2(x2,w3.y,acc[7]);
            }
        }
        __syncthreads();
    }
    // partial out, [kh][r][16]
    float4* dst = (float4*)g_part + ((size_t)kh*NTOT + row0 + t)*4;
    #pragma unroll
    for (int q = 0; q < 4; q++){
        float2 lo = unpack2(acc[2*q]), hi = unpack2(acc[2*q+1]);
        dst[q] = make_float4(lo.x, lo.y, hi.x, hi.y);
    }
}

// ---- reduce split-K4 partials + transpose to [n][b][16] layout ----
__global__ void k_red(){
    int i = blockIdx.x*256 + threadIdx.x;              // < NTOT*4 float4s
    if (i >= NTOT*4) return;
    const float4* P = (const float4*)g_part;
    float4 a = P[i];
    float4 b4 = P[NTOT*4 + i];
    float4 c = P[2*NTOT*4 + i];
    float4 d = P[3*NTOT*4 + i];
    float4 s = make_float4(((a.x+b4.x)+c.x)+d.x, ((a.y+b4.y)+c.y)+d.y,
                           ((a.z+b4.z)+c.z)+d.z, ((a.w+b4.w)+c.w)+d.w);
    int r = i >> 2, q = i & 3;
    int b = r / N_NODES, n = r - b*N_NODES;
    ((float4*)g_h1)[(n*16 + b)*4 + q] = s;
}

// ---- gather: buf[n][*] = dinv[n]^2 * h[n][*] + sum_{e: dst=n} norm_e * h[src_e][*] ----
// 64 threads per node (one float4 lane each), 8-deep unrolled edge loop. (proven)
__global__ void __launch_bounds__(256) k_gather(int layer){
    int gt = blockIdx.x*256 + threadIdx.x;
    int n = gt >> 6;
    int i = gt & 63;
    if (n >= N_NODES) return;
    const float4* __restrict__ h  = (const float4*)(layer ? g_h2  : g_h1);
    float4*       __restrict__ bf = (float4*)      (layer ? g_buf2 : g_buf1);
    float di = g_dinv[n];
    float sl = di * di;
    float4 v = h[n*64 + i];
    float4 acc = make_float4(v.x*sl, v.y*sl, v.z*sl, v.w*sl);
    int k   = g_rowstart[n];
    int end = g_rowstart[n+1];
    for (; k + 8 <= end; k += 8){
        int2 e0 = g_csr[k+0], e1 = g_csr[k+1], e2 = g_csr[k+2], e3 = g_csr[k+3];
        int2 e4 = g_csr[k+4], e5 = g_csr[k+5], e6 = g_csr[k+6], e7 = g_csr[k+7];
        float4 u0 = h[e0.x*64 + i], u1 = h[e1.x*64 + i], u2 = h[e2.x*64 + i], u3 = h[e3.x*64 + i];
        float4 u4 = h[e4.x*64 + i], u5 = h[e5.x*64 + i], u6 = h[e6.x*64 + i], u7 = h[e7.x*64 + i];
        fma4(acc, __int_as_float(e0.y), u0); fma4(acc, __int_as_float(e1.y), u1);
        fma4(acc, __int_as_float(e2.y), u2); fma4(acc, __int_as_float(e3.y), u3);
        fma4(acc, __int_as_float(e4.y), u4); fma4(acc, __int_as_float(e5.y), u5);
        fma4(acc, __int_as_float(e6.y), u6); fma4(acc, __int_as_float(e7.y), u7);
    }
    for (; k + 4 <= end; k += 4){
        int2 e0 = g_csr[k+0], e1 = g_csr[k+1], e2 = g_csr[k+2], e3 = g_csr[k+3];
        float4 u0 = h[e0.x*64 + i], u1 = h[e1.x*64 + i], u2 = h[e2.x*64 + i], u3 = h[e3.x*64 + i];
        fma4(acc, __int_as_float(e0.y), u0); fma4(acc, __int_as_float(e1.y), u1);
        fma4(acc, __int_as_float(e2.y), u2); fma4(acc, __int_as_float(e3.y), u3);
    }
    for (; k < end; k++){
        int2 e = g_csr[k];
        float4 u = h[e.x*64 + i];
        fma4(acc, __int_as_float(e.y), u);
    }
    bf[n*64 + i] = acc;
}

// ---- layer2 input transform: h2 = relu(buf1 + b1) @ W2 (proven) ----
__global__ void __launch_bounds__(256) k_xform2(const float* __restrict__ W2, const float* __restrict__ b1){
    __shared__ float sw[256];
    __shared__ float sb[16];
    sw[threadIdx.x] = W2[threadIdx.x];
    if (threadIdx.x < 16) sb[threadIdx.x] = b1[threadIdx.x];
    __syncthreads();
    int r = blockIdx.x*256 + threadIdx.x;
    if (r >= NTOT) return;
    const float4* in = (const float4*)g_buf1 + (size_t)r*4;
    float v[16];
    #pragma unroll
    for (int q=0;q<4;q++){
        float4 t = in[q];
        v[4*q+0]=t.x; v[4*q+1]=t.y; v[4*q+2]=t.z; v[4*q+3]=t.w;
    }
    #pragma unroll
    for (int j=0;j<16;j++) v[j] = fmaxf(v[j] + sb[j], 0.0f);
    float o[16];
    #pragma unroll
    for (int j=0;j<16;j++) o[j] = 0.0f;
    #pragma unroll
    for (int j=0;j<16;j++){
        float vj = v[j];
        #pragma unroll
        for (int jo=0;jo<16;jo++) o[jo] = fmaf(vj, sw[j*16+jo], o[jo]);
    }
    float4* out = (float4*)g_h2 + (size_t)r*4;
    #pragma unroll
    for (int q=0;q<4;q++)
        out[q] = make_float4(o[4*q+0], o[4*q+1], o[4*q+2], o[4*q+3]);
}

// ---- column MLP: 32 threads per row (j = lane&15, k-half = lane>>4) ----
__global__ void __launch_bounds__(256) k_colmlp(const float* __restrict__ CF, const float* __restrict__ cw1,
                                                const float* __restrict__ cb1, const float* __restrict__ cw2,
                                                const float* __restrict__ cb2){
    __shared__ __align__(16) float sw[FCOL*16];    // [k][j]
    __shared__ float sb1[16], sw2[16], scb2;
    for (int i = threadIdx.x; i < FCOL*16/4; i += 256)
        ((float4*)sw)[i] = ((const float4*)cw1)[i];
    if (threadIdx.x < 16){ sb1[threadIdx.x]=cb1[threadIdx.x]; sw2[threadIdx.x]=cw2[threadIdx.x]; }
    if (threadIdx.x == 0) scb2 = cb2[0];
    __syncthreads();
    int gt = blockIdx.x*256 + threadIdx.x;
    int r    = gt >> 5;        // row 0..1023
    int lane = gt & 31;
    int j    = lane & 15;      // hidden unit
    int hf   = lane >> 4;      // k-half
    const float4* xr = (const float4*)CF + (size_t)r*(FCOL/4) + hf*(FCOL/8);
    float acc = hf ? 0.0f : sb1[j];
    #pragma unroll
    for (int k4 = 0; k4 < FCOL/8; k4++){
        float4 xv = xr[k4];
        int kb = (hf*(FCOL/8) + k4)*4;
        acc = fmaf(xv.x, sw[(kb+0)*16 + j], acc);
        acc = fmaf(xv.y, sw[(kb+1)*16 + j], acc);
        acc = fmaf(xv.z, sw[(kb+2)*16 + j], acc);
        acc = fmaf(xv.w, sw[(kb+3)*16 + j], acc);
    }
    acc += __shfl_xor_sync(0xffffffffu, acc, 16);   // merge k-halves (same j)
    float val = fmaxf(acc, 0.0f) * sw2[j];
    val += __shfl_xor_sync(0xffffffffu, val, 1);
    val += __shfl_xor_sync(0xffffffffu, val, 2);
    val += __shfl_xor_sync(0xffffffffu, val, 4);
    val += __shfl_xor_sync(0xffffffffu, val, 8);
    if (lane == 0) g_col[r] = val + scb2;
}

// ---- final: node head + broadcast add with col logits (proven) ----
__global__ void __launch_bounds__(256) k_final(const float* __restrict__ b2, const float* __restrict__ fcw,
                                               const float* __restrict__ fcb, float* __restrict__ out){
    __shared__ __align__(16) float scol[BATCH*NCOL];
    __shared__ float sb2[16], sfw[16];
    for (int i = threadIdx.x; i < BATCH*NCOL; i += 256) scol[i] = g_col[i];
    if (threadIdx.x < 16){ sb2[threadIdx.x]=b2[threadIdx.x]; sfw[threadIdx.x]=fcw[threadIdx.x]; }
    __syncthreads();
    int r = blockIdx.x*256 + threadIdx.x;
    if (r >= NTOT) return;
    int b = r / N_NODES, n = r - b*N_NODES;
    const float4* in = (const float4*)g_buf2 + ((size_t)n*16 + b)*4;
    float logit = fcb[0];
    #pragma unroll
    for (int q=0;q<4;q++){
        float4 t = in[q];
        logit = fmaf(fmaxf(t.x + sb2[4*q+0], 0.0f), sfw[4*q+0], logit);
        logit = fmaf(fmaxf(t.y + sb2[4*q+1], 0.0f), sfw[4*q+1], logit);
        logit = fmaf(fmaxf(t.z + sb2[4*q+2], 0.0f), sfw[4*q+2], logit);
        logit = fmaf(fmaxf(t.w + sb2[4*q+3], 0.0f), sfw[4*q+3], logit);
    }
    float4* o = (float4*)out + (size_t)r*16;          // out[b][n*64 + c]
    const float4* sc = (const float4*)scol + b*16;
    #pragma unroll
    for (int c4 = 0; c4 < 16; c4++){
        float4 cv = sc[c4];
        o[c4] = make_float4(logit+cv.x, logit+cv.y, logit+cv.z, logit+cv.w);
    }
}

extern "C" void kernel_launch(void* const* d_in, const int* in_sizes, int n_in,
                              void* d_out, int out_size){
    const float* X   = (const float*)d_in[0];
    const float* CF  = (const float*)d_in[1];
    const int*   ei  = (const int*)d_in[2];
    const float* W1  = (const float*)d_in[3];
    const float* b1  = (const float*)d_in[4];
    const float* W2  = (const float*)d_in[5];
    const float* b2  = (const float*)d_in[6];
    const float* fcw = (const float*)d_in[7];
    const float* fcb = (const float*)d_in[8];
    const float* cw1 = (const float*)d_in[9];
    const float* cb1 = (const float*)d_in[10];
    const float* cw2 = (const float*)d_in[11];
    const float* cb2 = (const float*)d_in[12];
    float* out = (float*)d_out;

    // k_gemm1 is launch #4 — profiled next round.
    k_count <<<(NEDGE/4+255)/256, 256>>>(ei);
    k_scan  <<<1, 1024>>>();
    k_fill  <<<(NEDGE/2+255)/256, 256>>>(ei);
    k_gemm1 <<<dim3(NTOT/GR, KSPLIT), GR>>>(X, W1);
    k_red   <<<(NTOT*4+255)/256, 256>>>();
    k_gather<<<(N_NODES*64)/256 + 1, 256>>>(0);
    k_xform2<<<(NTOT+255)/256, 256>>>(W2, b1);
    k_gather<<<(N_NODES*64)/256 + 1, 256>>>(1);
    k_colmlp<<<(BATCH*NCOL*32)/256, 256>>>(CF, cw1, cb1, cw2, cb2);
    k_final <<<(NTOT+255)/256, 256>>>(b2, fcw, fcb, out);
}

// round 11
// speedup vs baseline: 1.9204x; 1.0229x over previous
#include <cuda_runtime.h>
#include <cstdint>

#define N_NODES 5000
#define BATCH   16
#define FEAT    512
#define NEDGE   160000
#define NCOL    64
#define FCOL    128
#define NTOT    (N_NODES*BATCH)   // 80000

// Scratch (device globals; zero-initialized at load; no allocation allowed)
__device__ __align__(16) float g_h1  [N_NODES*BATCH*16];
__device__ __align__(16) float g_buf1[N_NODES*BATCH*16];
__device__ __align__(16) float g_h2  [N_NODES*BATCH*16];
__device__ __align__(16) float g_buf2[N_NODES*BATCH*16];
__device__ __align__(16) float g_part[4*N_NODES*BATCH*16];  // split-K4 partials, [kh][r][16]
__device__ int   g_deg [N_NODES];          // zero at entry (re-zeroed in k_gemm1 each run)
__device__ int   g_cursor[N_NODES];        // ditto
__device__ int   g_rowstart[N_NODES+1];
__device__ float g_dinv[N_NODES];
__device__ __align__(16) int2 g_csr[NEDGE];   // x = src node, y = norm (float bits)
__device__ float g_col [BATCH*NCOL];

// ---- packed f32x2 helpers (Blackwell) ----
__device__ __forceinline__ unsigned long long splat2(float x){
    unsigned long long r; asm("mov.b64 %0, {%1, %1};" : "=l"(r) : "f"(x)); return r;
}
__device__ __forceinline__ unsigned long long ffma2(unsigned long long a, unsigned long long b, unsigned long long c){
    unsigned long long d; asm("fma.rn.f32x2 %0, %1, %2, %3;" : "=l"(d) : "l"(a), "l"(b), "l"(c)); return d;
}
__device__ __forceinline__ float2 unpack2(unsigned long long v){
    float2 r; asm("mov.b64 {%0, %1}, %2;" : "=f"(r.x), "=f"(r.y) : "l"(v)); return r;
}
__device__ __forceinline__ void fma4(float4& a, float nr, const float4& u){
    a.x = fmaf(nr, u.x, a.x); a.y = fmaf(nr, u.y, a.y);
    a.z = fmaf(nr, u.z, a.z); a.w = fmaf(nr, u.w, a.w);
}
__device__ __forceinline__ void cpasync16(uint32_t saddr, const void* gptr){
    asm volatile("cp.async.cg.shared.global [%0], [%1], 16;" :: "r"(saddr), "l"(gptr));
}

// edge_index is INT32 (proven). Layout [2, E]: src = ei[0..E), dst = ei[E..2E).

// ---- degree count: 4 edges per thread via int4 over the dst half ----
__global__ void k_count(const int* __restrict__ ei){
    int e4 = blockIdx.x*blockDim.x + threadIdx.x;
    if (e4 < NEDGE/4){
        int4 v = ((const int4*)(ei + NEDGE))[e4];
        atomicAdd(&g_deg[v.x], 1);
        atomicAdd(&g_deg[v.y], 1);
        atomicAdd(&g_deg[v.z], 1);
        atomicAdd(&g_deg[v.w], 1);
    }
}
// single-block exclusive scan over 5000 degree counts (+ dinv)
__global__ void __launch_bounds__(1024) k_scan(){
    __shared__ int part[1024];
    int t = threadIdx.x;
    const int CH = (N_NODES + 1023) / 1024;   // 5
    int base = t * CH;
    int s = 0;
    #pragma unroll
    for (int j = 0; j < CH; j++){ int idx = base + j; if (idx < N_NODES) s += g_deg[idx]; }
    part[t] = s; __syncthreads();
    for (int off = 1; off < 1024; off <<= 1){
        int v = (t >= off) ? part[t - off] : 0;
        __syncthreads();
        part[t] += v;
        __syncthreads();
    }
    int excl = (t == 0) ? 0 : part[t - 1];
    #pragma unroll
    for (int j = 0; j < CH; j++){
        int idx = base + j;
        if (idx < N_NODES){
            int d = g_deg[idx];
            g_rowstart[idx] = excl; excl += d;
            g_dinv[idx] = rsqrtf((float)(d + 1));
        }
    }
    if (t == 0) g_rowstart[N_NODES] = NEDGE;
}
// CSR fill: 2 edges per thread via int2 loads
__global__ void k_fill(const int* __restrict__ ei){
    int e2 = blockIdx.x*blockDim.x + threadIdx.x;
    if (e2 >= NEDGE/2) return;
    int2 sp = ((const int2*)ei)[e2];
    int2 dp = ((const int2*)(ei + NEDGE))[e2];
    {
        int pos = atomicAdd(&g_cursor[dp.x], 1);
        g_csr[g_rowstart[dp.x] + pos] = make_int2(sp.x, __float_as_int(g_dinv[sp.x]*g_dinv[dp.x]));
    }
    {
        int pos = atomicAdd(&g_cursor[dp.y], 1);
        g_csr[g_rowstart[dp.y] + pos] = make_int2(sp.y, __float_as_int(g_dinv[sp.y]*g_dinv[dp.y]));
    }
}

// ---- GEMM1 split-K4, cp.async, WARP-AUTONOMOUS double-buffered staging ----
// grid (625, 4); block 128 (4 warps). Each warp owns 32 rows + its own 2 tile buffers.
// No block barriers in the mainloop — only cp.async.wait_group + __syncwarp.
#define GR 128
#define KC 16
#define KSPLIT 4
#define KQ (FEAT/KSPLIT)        // 128
#define CHUNKS (KQ/KC)          // 8
#define TSTRIDE 20
#define WTILE (32*TSTRIDE)      // floats per warp-buffer (2560 B)
__global__ void __launch_bounds__(GR, 8) k_gemm1(const float* __restrict__ X, const float* __restrict__ W1){
    __shared__ __align__(16) float ws[KQ*16];                 // 8 KB (this k-quarter of W)
    __shared__ __align__(16) float tile[4][2][WTILE];         // 4 warps x 2 bufs x 2.5 KB
    int t    = threadIdx.x;
    int w    = t >> 5;
    int lane = t & 31;
    int kh   = blockIdx.y;
    if (kh == 0){
        int gid = blockIdx.x*GR + t;
        if (gid < N_NODES){ g_deg[gid] = 0; g_cursor[gid] = 0; }
    }
    const float4* W14 = (const float4*)W1 + kh*(KQ*16/4);
    for (int i = t; i < KQ*16/4; i += GR)
        ((float4*)ws)[i] = W14[i];
    int wrow0 = blockIdx.x * GR + w*32;                       // this warp's 32 rows
    const float4* Xw = (const float4*)X + (size_t)wrow0*(FEAT/4) + kh*(KQ/4);
    // per-lane staging coordinates (4 float4 slots per chunk)
    int rr[4], kq[4];
    #pragma unroll
    for (int i = 0; i < 4; i++){
        int f = lane + 32*i;
        rr[i] = f >> 2; kq[i] = f & 3;
    }
    uint32_t tb[2];
    tb[0] = (uint32_t)__cvta_generic_to_shared(&tile[w][0][0]);
    tb[1] = (uint32_t)__cvta_generic_to_shared(&tile[w][1][0]);
    // prologue: chunk 0 -> buf 0
    #pragma unroll
    for (int i = 0; i < 4; i++)
        cpasync16(tb[0] + (rr[i]*TSTRIDE + kq[i]*4)*4, Xw + (size_t)rr[i]*(FEAT/4) + kq[i]);
    asm volatile("cp.async.commit_group;" ::: "memory");
    __syncthreads();   // ws visible to all warps (also covers deg/cursor re-zero ordering)
    unsigned long long acc[8] = {0,0,0,0,0,0,0,0};
    for (int c = 0; c < CHUNKS; c++){
        if (c + 1 < CHUNKS){
            uint32_t dstb = tb[(c+1)&1];
            #pragma unroll
            for (int i = 0; i < 4; i++)
                cpasync16(dstb + (rr[i]*TSTRIDE + kq[i]*4)*4,
                          Xw + (size_t)rr[i]*(FEAT/4) + (c+1)*4 + kq[i]);
            asm volatile("cp.async.commit_group;" ::: "memory");
            asm volatile("cp.async.wait_group 1;" ::: "memory");
        } else {
            asm volatile("cp.async.wait_group 0;" ::: "memory");
        }
        __syncwarp();                      // warp-local visibility of staged tile
        const float* tl = &tile[w][c&1][0];
        #pragma unroll
        for (int q = 0; q < 4; q++){
            float4 xv = *((const float4*)&tl[lane*TSTRIDE + q*4]);
            int kbase = c*KC + q*4;
            #pragma unroll
            for (int kk = 0; kk < 4; kk++){
                float xs = (kk==0)?xv.x:(kk==1)?xv.y:(kk==2)?xv.z:xv.w;
                unsigned long long x2 = splat2(xs);
                const ulonglong2* wk = (const ulonglong2*)&ws[(kbase+kk)*16];
                ulonglong2 w0 = wk[0], w1 = wk[1], w2 = wk[2], w3 = wk[3];
                acc[0]=ffma2(x2,w0.x,acc[0]); acc[1]=ffma2(x2,w0.y,acc[1]);
                acc[2]=ffma2(x2,w1.x,acc[2]); acc[3]=ffma2(x2,w1.y,acc[3]);
                acc[4]=ffma2(x2,w2.x,acc[4]); acc[5]=ffma2(x2,w2.y,acc[5]);
                acc[6]=ffma2(x2,w3.x,acc[6]); acc[7]=ffma2(x2,w3.y,acc[7]);
            }
        }
        __syncwarp();                      // staged buffer free for reuse
    }
    // partial out, [kh][r][16]
    float4* dst = (float4*)g_part + ((size_t)kh*NTOT + wrow0 + lane)*4;
    #pragma unroll
    for (int q = 0; q < 4; q++){
        float2 lo = unpack2(acc[2*q]), hi = unpack2(acc[2*q+1]);
        dst[q] = make_float4(lo.x, lo.y, hi.x, hi.y);
    }
}

// ---- reduce split-K4 partials + transpose to [n][b][16] layout ----
__global__ void k_red(){
    int i = blockIdx.x*256 + threadIdx.x;              // < NTOT*4 float4s
    if (i >= NTOT*4) return;
    const float4* P = (const float4*)g_part;
    float4 a = P[i];
    float4 b4 = P[NTOT*4 + i];
    float4 c = P[2*NTOT*4 + i];
    float4 d = P[3*NTOT*4 + i];
    float4 s = make_float4(((a.x+b4.x)+c.x)+d.x, ((a.y+b4.y)+c.y)+d.y,
                           ((a.z+b4.z)+c.z)+d.z, ((a.w+b4.w)+c.w)+d.w);
    int r = i >> 2, q = i & 3;
    int b = r / N_NODES, n = r - b*N_NODES;
    ((float4*)g_h1)[(n*16 + b)*4 + q] = s;
}

// ---- gather: buf[n][*] = dinv[n]^2 * h[n][*] + sum_{e: dst=n} norm_e * h[src_e][*] ----
__global__ void __launch_bounds__(256) k_gather(int layer){
    int gt = blockIdx.x*256 + threadIdx.x;
    int n = gt >> 6;
    int i = gt & 63;
    if (n >= N_NODES) return;
    const float4* __restrict__ h  = (const float4*)(layer ? g_h2  : g_h1);
    float4*       __restrict__ bf = (float4*)      (layer ? g_buf2 : g_buf1);
    float di = g_dinv[n];
    float sl = di * di;
    float4 v = h[n*64 + i];
    float4 acc = make_float4(v.x*sl, v.y*sl, v.z*sl, v.w*sl);
    int k   = g_rowstart[n];
    int end = g_rowstart[n+1];
    for (; k + 8 <= end; k += 8){
        int2 e0 = g_csr[k+0], e1 = g_csr[k+1], e2 = g_csr[k+2], e3 = g_csr[k+3];
        int2 e4 = g_csr[k+4], e5 = g_csr[k+5], e6 = g_csr[k+6], e7 = g_csr[k+7];
        float4 u0 = h[e0.x*64 + i], u1 = h[e1.x*64 + i], u2 = h[e2.x*64 + i], u3 = h[e3.x*64 + i];
        float4 u4 = h[e4.x*64 + i], u5 = h[e5.x*64 + i], u6 = h[e6.x*64 + i], u7 = h[e7.x*64 + i];
        fma4(acc, __int_as_float(e0.y), u0); fma4(acc, __int_as_float(e1.y), u1);
        fma4(acc, __int_as_float(e2.y), u2); fma4(acc, __int_as_float(e3.y), u3);
        fma4(acc, __int_as_float(e4.y), u4); fma4(acc, __int_as_float(e5.y), u5);
        fma4(acc, __int_as_float(e6.y), u6); fma4(acc, __int_as_float(e7.y), u7);
    }
    for (; k + 4 <= end; k += 4){
        int2 e0 = g_csr[k+0], e1 = g_csr[k+1], e2 = g_csr[k+2], e3 = g_csr[k+3];
        float4 u0 = h[e0.x*64 + i], u1 = h[e1.x*64 + i], u2 = h[e2.x*64 + i], u3 = h[e3.x*64 + i];
        fma4(acc, __int_as_float(e0.y), u0); fma4(acc, __int_as_float(e1.y), u1);
        fma4(acc, __int_as_float(e2.y), u2); fma4(acc, __int_as_float(e3.y), u3);
    }
    for (; k < end; k++){
        int2 e = g_csr[k];
        float4 u = h[e.x*64 + i];
        fma4(acc, __int_as_float(e.y), u);
    }
    bf[n*64 + i] = acc;
}

// ---- layer2 input transform: h2 = relu(buf1 + b1) @ W2 (proven) ----
__global__ void __launch_bounds__(256) k_xform2(const float* __restrict__ W2, const float* __restrict__ b1){
    __shared__ float sw[256];
    __shared__ float sb[16];
    sw[threadIdx.x] = W2[threadIdx.x];
    if (threadIdx.x < 16) sb[threadIdx.x] = b1[threadIdx.x];
    __syncthreads();
    int r = blockIdx.x*256 + threadIdx.x;
    if (r >= NTOT) return;
    const float4* in = (const float4*)g_buf1 + (size_t)r*4;
    float v[16];
    #pragma unroll
    for (int q=0;q<4;q++){
        float4 t = in[q];
        v[4*q+0]=t.x; v[4*q+1]=t.y; v[4*q+2]=t.z; v[4*q+3]=t.w;
    }
    #pragma unroll
    for (int j=0;j<16;j++) v[j] = fmaxf(v[j] + sb[j], 0.0f);
    float o[16];
    #pragma unroll
    for (int j=0;j<16;j++) o[j] = 0.0f;
    #pragma unroll
    for (int j=0;j<16;j++){
        float vj = v[j];
        #pragma unroll
        for (int jo=0;jo<16;jo++) o[jo] = fmaf(vj, sw[j*16+jo], o[jo]);
    }
    float4* out = (float4*)g_h2 + (size_t)r*4;
    #pragma unroll
    for (int q=0;q<4;q++)
        out[q] = make_float4(o[4*q+0], o[4*q+1], o[4*q+2], o[4*q+3]);
}

// ---- column MLP: 32 threads per row (proven) ----
__global__ void __launch_bounds__(256) k_colmlp(const float* __restrict__ CF, const float* __restrict__ cw1,
                                                const float* __restrict__ cb1, const float* __restrict__ cw2,
                                                const float* __restrict__ cb2){
    __shared__ __align__(16) float sw[FCOL*16];    // [k][j]
    __shared__ float sb1[16], sw2[16], scb2;
    for (int i = threadIdx.x; i < FCOL*16/4; i += 256)
        ((float4*)sw)[i] = ((const float4*)cw1)[i];
    if (threadIdx.x < 16){ sb1[threadIdx.x]=cb1[threadIdx.x]; sw2[threadIdx.x]=cw2[threadIdx.x]; }
    if (threadIdx.x == 0) scb2 = cb2[0];
    __syncthreads();
    int gt = blockIdx.x*256 + threadIdx.x;
    int r    = gt >> 5;        // row 0..1023
    int lane = gt & 31;
    int j    = lane & 15;      // hidden unit
    int hf   = lane >> 4;      // k-half
    const float4* xr = (const float4*)CF + (size_t)r*(FCOL/4) + hf*(FCOL/8);
    float acc = hf ? 0.0f : sb1[j];
    #pragma unroll
    for (int k4 = 0; k4 < FCOL/8; k4++){
        float4 xv = xr[k4];
        int kb = (hf*(FCOL/8) + k4)*4;
        acc = fmaf(xv.x, sw[(kb+0)*16 + j], acc);
        acc = fmaf(xv.y, sw[(kb+1)*16 + j], acc);
        acc = fmaf(xv.z, sw[(kb+2)*16 + j], acc);
        acc = fmaf(xv.w, sw[(kb+3)*16 + j], acc);
    }
    acc += __shfl_xor_sync(0xffffffffu, acc, 16);   // merge k-halves (same j)
    float val = fmaxf(acc, 0.0f) * sw2[j];
    val += __shfl_xor_sync(0xffffffffu, val, 1);
    val += __shfl_xor_sync(0xffffffffu, val, 2);
    val += __shfl_xor_sync(0xffffffffu, val, 4);
    val += __shfl_xor_sync(0xffffffffu, val, 8);
    if (lane == 0) g_col[r] = val + scb2;
}

// ---- final: node head + broadcast add with col logits (proven) ----
__global__ void __launch_bounds__(256) k_final(const float* __restrict__ b2, const float* __restrict__ fcw,
                                               const float* __restrict__ fcb, float* __restrict__ out){
    __shared__ __align__(16) float scol[BATCH*NCOL];
    __shared__ float sb2[16], sfw[16];
    for (int i = threadIdx.x; i < BATCH*NCOL; i += 256) scol[i] = g_col[i];
    if (threadIdx.x < 16){ sb2[threadIdx.x]=b2[threadIdx.x]; sfw[threadIdx.x]=fcw[threadIdx.x]; }
    __syncthreads();
    int r = blockIdx.x*256 + threadIdx.x;
    if (r >= NTOT) return;
    int b = r / N_NODES, n = r - b*N_NODES;
    const float4* in = (const float4*)g_buf2 + ((size_t)n*16 + b)*4;
    float logit = fcb[0];
    #pragma unroll
    for (int q=0;q<4;q++){
        float4 t = in[q];
        logit = fmaf(fmaxf(t.x + sb2[4*q+0], 0.0f), sfw[4*q+0], logit);
        logit = fmaf(fmaxf(t.y + sb2[4*q+1], 0.0f), sfw[4*q+1], logit);
        logit = fmaf(fmaxf(t.z + sb2[4*q+2], 0.0f), sfw[4*q+2], logit);
        logit = fmaf(fmaxf(t.w + sb2[4*q+3], 0.0f), sfw[4*q+3], logit);
    }
    float4* o = (float4*)out + (size_t)r*16;          // out[b][n*64 + c]
    const float4* sc = (const float4*)scol + b*16;
    #pragma unroll
    for (int c4 = 0; c4 < 16; c4++){
        float4 cv = sc[c4];
        o[c4] = make_float4(logit+cv.x, logit+cv.y, logit+cv.z, logit+cv.w);
    }
}

extern "C" void kernel_launch(void* const* d_in, const int* in_sizes, int n_in,
                              void* d_out, int out_size){
    const float* X   = (const float*)d_in[0];
    const float* CF  = (const float*)d_in[1];
    const int*   ei  = (const int*)d_in[2];
    const float* W1  = (const float*)d_in[3];
    const float* b1  = (const float*)d_in[4];
    const float* W2  = (const float*)d_in[5];
    const float* b2  = (const float*)d_in[6];
    const float* fcw = (const float*)d_in[7];
    const float* fcb = (const float*)d_in[8];
    const float* cw1 = (const float*)d_in[9];
    const float* cb1 = (const float*)d_in[10];
    const float* cw2 = (const float*)d_in[11];
    const float* cb2 = (const float*)d_in[12];
    float* out = (float*)d_out;

    // k_gemm1 is launch #4 — profiled next round.
    k_count <<<(NEDGE/4+255)/256, 256>>>(ei);
    k_scan  <<<1, 1024>>>();
    k_fill  <<<(NEDGE/2+255)/256, 256>>>(ei);
    k_gemm1 <<<dim3(NTOT/GR, KSPLIT), GR>>>(X, W1);
    k_red   <<<(NTOT*4+255)/256, 256>>>();
    k_gather<<<(N_NODES*64)/256 + 1, 256>>>(0);
    k_xform2<<<(NTOT+255)/256, 256>>>(W2, b1);
    k_gather<<<(N_NODES*64)/256 + 1, 256>>>(1);
    k_colmlp<<<(BATCH*NCOL*32)/256, 256>>>(CF, cw1, cb1, cw2, cb2);
    k_final <<<(NTOT+255)/256, 256>>>(b2, fcw, fcb, out);
}